// round 4
// baseline (speedup 1.0000x reference)
#include <cuda_runtime.h>
#include <math.h>

// Problem constants
#define B_  2
#define N_  2048
#define D_  1024
#define H_  16
#define DH_ 64
#define DI_ 1024
#define SCALE_ 0.125f   // 64^-0.5

// Scratch (device globals: allocation-free per harness rules)
__device__ float g_q[B_*H_*N_*DH_];      // [b,h,n,dh], scale folded in
__device__ float g_k[B_*H_*N_*DH_];
__device__ float g_v[B_*H_*N_*DH_];
__device__ float g_att[B_*N_*DI_];       // attention out, token-major
__device__ float g_gated[B_*N_*DI_];     // gated attention out

// ---------------------------------------------------------------------------
// SGEMM: C[M,NN] = A[M,K] @ W[K,NN], 128x128x8 tiles, 8x8 per thread.
// MODE 0: Q proj  -> g_q (head split, *SCALE)
// MODE 1: KV proj -> g_k / g_v (head split)
// MODE 2: gate    -> g_gated = g_att * sigmoid(acc + bg)
// MODE 3: out     -> out = g_gated @ Wo  (A param ignored; reads g_gated)
// ---------------------------------------------------------------------------
template<int MODE>
__global__ void __launch_bounds__(256, 2) sgemm_kernel(
    const float* __restrict__ A, const float* __restrict__ W,
    int K, int NN, const float* __restrict__ bg, float* __restrict__ out)
{
    __shared__ float As[8][128];
    __shared__ float Bs[8][128];

    const float* Aptr = (MODE == 3) ? g_gated : A;

    const int tid = threadIdx.x;
    const int tx  = tid & 15;         // 0..15
    const int ty  = tid >> 4;         // 0..15
    const int row0 = blockIdx.y * 128;
    const int col0 = blockIdx.x * 128;

    const int arow = tid >> 1;            // 0..127
    const int acol = (tid & 1) * 4;       // 0 or 4
    const int brow = tid >> 5;            // 0..7
    const int bcol = (tid & 31) * 4;      // 0..124

    float acc[8][8];
    #pragma unroll
    for (int i = 0; i < 8; i++)
        #pragma unroll
        for (int j = 0; j < 8; j++) acc[i][j] = 0.f;

    for (int k0 = 0; k0 < K; k0 += 8) {
        float4 a = *(const float4*)&Aptr[(size_t)(row0 + arow) * K + k0 + acol];
        As[acol + 0][arow] = a.x;
        As[acol + 1][arow] = a.y;
        As[acol + 2][arow] = a.z;
        As[acol + 3][arow] = a.w;
        float4 b = *(const float4*)&W[(size_t)(k0 + brow) * NN + col0 + bcol];
        *(float4*)&Bs[brow][bcol] = b;
        __syncthreads();

        #pragma unroll
        for (int kk = 0; kk < 8; kk++) {
            float ra[8], rb[8];
            *(float4*)&ra[0] = *(const float4*)&As[kk][ty * 8];
            *(float4*)&ra[4] = *(const float4*)&As[kk][ty * 8 + 4];
            *(float4*)&rb[0] = *(const float4*)&Bs[kk][tx * 8];
            *(float4*)&rb[4] = *(const float4*)&Bs[kk][tx * 8 + 4];
            #pragma unroll
            for (int i = 0; i < 8; i++)
                #pragma unroll
                for (int j = 0; j < 8; j++)
                    acc[i][j] += ra[i] * rb[j];
        }
        __syncthreads();
    }

    // Epilogues
    #pragma unroll
    for (int i = 0; i < 8; i++) {
        const int m  = row0 + ty * 8 + i;
        const int bb = m >> 11;            // m / 2048
        const int ii = m & 2047;
        #pragma unroll
        for (int jv = 0; jv < 2; jv++) {
            const int c0 = col0 + tx * 8 + jv * 4;
            float4 v;
            v.x = acc[i][jv * 4 + 0];
            v.y = acc[i][jv * 4 + 1];
            v.z = acc[i][jv * 4 + 2];
            v.w = acc[i][jv * 4 + 3];
            if (MODE == 0) {
                const int h = c0 >> 6, d = c0 & 63;
                v.x *= SCALE_; v.y *= SCALE_; v.z *= SCALE_; v.w *= SCALE_;
                *(float4*)&g_q[(((size_t)(bb * H_ + h)) * N_ + ii) * DH_ + d] = v;
            } else if (MODE == 1) {
                if (c0 < DI_) {
                    const int h = c0 >> 6, d = c0 & 63;
                    *(float4*)&g_k[(((size_t)(bb * H_ + h)) * N_ + ii) * DH_ + d] = v;
                } else {
                    const int c = c0 - DI_;
                    const int h = c >> 6, d = c & 63;
                    *(float4*)&g_v[(((size_t)(bb * H_ + h)) * N_ + ii) * DH_ + d] = v;
                }
            } else if (MODE == 2) {
                const size_t idx = (size_t)m * DI_ + c0;
                float4 ao = *(const float4*)&g_att[idx];
                float4 bgv = *(const float4*)&bg[c0];
                v.x = ao.x * (1.f / (1.f + expf(-(v.x + bgv.x))));
                v.y = ao.y * (1.f / (1.f + expf(-(v.y + bgv.y))));
                v.z = ao.z * (1.f / (1.f + expf(-(v.z + bgv.z))));
                v.w = ao.w * (1.f / (1.f + expf(-(v.w + bgv.w))));
                *(float4*)&g_gated[idx] = v;
            } else { // MODE 3
                *(float4*)&out[(size_t)m * D_ + c0] = v;
            }
        }
    }
}

// ---------------------------------------------------------------------------
// Flash-style attention: one block = one (b,h) x 64 query rows.
// 256 threads as 16x16; each thread owns 4x4 of S and 4x4 of O.
// Online softmax with running (m, l). Mask applied additively (-1e30).
// ---------------------------------------------------------------------------
#define ATT_SMEM_FLOATS (4 * 64 * 68 + 64)

__global__ void __launch_bounds__(256, 2) attn_kernel(
    const float* __restrict__ bias, const int* __restrict__ mask)
{
    extern __shared__ float sm[];
    float* Qs = sm;                 // [64][68], transposed: Qs[d][m]
    float* Ks = Qs + 64 * 68;       // [64][68], transposed: Ks[d][n]
    float* Vs = Ks + 64 * 68;       // [64][68], natural:    Vs[j][d]
    float* Ps = Vs + 64 * 68;       // [64][68], transposed: Ps[j][m]
    float* mskf = Ps + 64 * 68;     // [64] additive mask

    const int tid = threadIdx.x;
    const int tx = tid & 15;
    const int ty = tid >> 4;
    const int bh = blockIdx.y;          // b*H + h
    const int b  = bh >> 4;
    const int h  = bh & 15;
    const int i0 = blockIdx.x * 64;

    const float* qptr = g_q + ((size_t)bh * N_ + i0) * DH_;
    const float* kbase = g_k + (size_t)bh * N_ * DH_;
    const float* vbase = g_v + (size_t)bh * N_ * DH_;
    const float* bptr = bias + ((size_t)bh * N_ + i0) * N_;

    // Load Q tile transposed: Qs[d][r]
    #pragma unroll
    for (int rep = 0; rep < 4; rep++) {
        const int idx = rep * 256 + tid;
        const int r = idx >> 4;
        const int d4 = (idx & 15) * 4;
        float4 q = *(const float4*)&qptr[(size_t)r * DH_ + d4];
        Qs[(d4 + 0) * 68 + r] = q.x;
        Qs[(d4 + 1) * 68 + r] = q.y;
        Qs[(d4 + 2) * 68 + r] = q.z;
        Qs[(d4 + 3) * 68 + r] = q.w;
    }

    float Oacc[4][4];
    float mi[4], li[4];
    #pragma unroll
    for (int mm = 0; mm < 4; mm++) {
        mi[mm] = -1e30f; li[mm] = 0.f;
        #pragma unroll
        for (int dd = 0; dd < 4; dd++) Oacc[mm][dd] = 0.f;
    }

    for (int t = 0; t < N_ / 64; t++) {
        const int j0 = t * 64;
        __syncthreads();  // protect Ks/Vs/Ps reuse from previous iter
        #pragma unroll
        for (int rep = 0; rep < 4; rep++) {
            const int idx = rep * 256 + tid;
            const int r = idx >> 4;
            const int d4 = (idx & 15) * 4;
            float4 kv = *(const float4*)&kbase[(size_t)(j0 + r) * DH_ + d4];
            Ks[(d4 + 0) * 68 + r] = kv.x;
            Ks[(d4 + 1) * 68 + r] = kv.y;
            Ks[(d4 + 2) * 68 + r] = kv.z;
            Ks[(d4 + 3) * 68 + r] = kv.w;
            float4 vv = *(const float4*)&vbase[(size_t)(j0 + r) * DH_ + d4];
            *(float4*)&Vs[r * 68 + d4] = vv;
        }
        if (tid < 64)
            mskf[tid] = (mask[(size_t)b * N_ + j0 + tid] != 0) ? 0.f : -1e30f;
        __syncthreads();

        // S = Q @ K^T (scale already folded into Q)
        float S[4][4];
        #pragma unroll
        for (int mm = 0; mm < 4; mm++)
            #pragma unroll
            for (int nn = 0; nn < 4; nn++) S[mm][nn] = 0.f;

        #pragma unroll 16
        for (int d = 0; d < 64; d++) {
            float qa[4], kb[4];
            *(float4*)qa = *(const float4*)&Qs[d * 68 + ty * 4];
            *(float4*)kb = *(const float4*)&Ks[d * 68 + tx * 4];
            #pragma unroll
            for (int mm = 0; mm < 4; mm++)
                #pragma unroll
                for (int nn = 0; nn < 4; nn++)
                    S[mm][nn] += qa[mm] * kb[nn];
        }

        // bias + mask, row max
        float rmax[4];
        #pragma unroll
        for (int mm = 0; mm < 4; mm++) {
            float4 bv = *(const float4*)&bptr[(size_t)(ty * 4 + mm) * N_ + j0 + tx * 4];
            S[mm][0] += bv.x + mskf[tx * 4 + 0];
            S[mm][1] += bv.y + mskf[tx * 4 + 1];
            S[mm][2] += bv.z + mskf[tx * 4 + 2];
            S[mm][3] += bv.w + mskf[tx * 4 + 3];
            float r = fmaxf(fmaxf(S[mm][0], S[mm][1]), fmaxf(S[mm][2], S[mm][3]));
            #pragma unroll
            for (int o = 1; o < 16; o <<= 1)
                r = fmaxf(r, __shfl_xor_sync(0xffffffffu, r, o));
            rmax[mm] = r;
        }

        // Online softmax update + write P (transposed)
        #pragma unroll
        for (int mm = 0; mm < 4; mm++) {
            const float mnew = fmaxf(mi[mm], rmax[mm]);
            const float corr = expf(mi[mm] - mnew);
            mi[mm] = mnew;
            li[mm] *= corr;
            #pragma unroll
            for (int dd = 0; dd < 4; dd++) Oacc[mm][dd] *= corr;
            float rsum = 0.f;
            #pragma unroll
            for (int nn = 0; nn < 4; nn++) {
                const float p = expf(S[mm][nn] - mnew);
                S[mm][nn] = p;
                rsum += p;
            }
            #pragma unroll
            for (int o = 1; o < 16; o <<= 1)
                rsum += __shfl_xor_sync(0xffffffffu, rsum, o);
            li[mm] += rsum;
            #pragma unroll
            for (int nn = 0; nn < 4; nn++)
                Ps[(tx * 4 + nn) * 68 + ty * 4 + mm] = S[mm][nn];
        }
        __syncthreads();

        // O += P @ V
        #pragma unroll 16
        for (int j = 0; j < 64; j++) {
            float pa[4], vb[4];
            *(float4*)pa = *(const float4*)&Ps[j * 68 + ty * 4];
            *(float4*)vb = *(const float4*)&Vs[j * 68 + tx * 4];
            #pragma unroll
            for (int mm = 0; mm < 4; mm++)
                #pragma unroll
                for (int dd = 0; dd < 4; dd++)
                    Oacc[mm][dd] += pa[mm] * vb[dd];
        }
    }

    // Normalize + write token-major [b, i, h*64 + d]
    #pragma unroll
    for (int mm = 0; mm < 4; mm++) {
        const float inv = 1.f / li[mm];
        float4 v;
        v.x = Oacc[mm][0] * inv;
        v.y = Oacc[mm][1] * inv;
        v.z = Oacc[mm][2] * inv;
        v.w = Oacc[mm][3] * inv;
        const size_t row = (size_t)b * N_ + i0 + ty * 4 + mm;
        *(float4*)&g_att[row * DI_ + h * DH_ + tx * 4] = v;
    }
}

// ---------------------------------------------------------------------------
extern "C" void kernel_launch(void* const* d_in, const int* in_sizes, int n_in,
                              void* d_out, int out_size)
{
    const float* seq  = (const float*)d_in[0];
    const int*   mask = (const int*)d_in[1];      // bool serialized as int32 (or f32 {0,1.0} — nonzero test covers both)
    const float* bias = (const float*)d_in[2];
    const float* Wq   = (const float*)d_in[3];
    const float* Wkv  = (const float*)d_in[4];
    const float* Wo   = (const float*)d_in[5];
    const float* Wg   = (const float*)d_in[6];
    const float* bg   = (const float*)d_in[7];
    float* out = (float*)d_out;

    const int smem_bytes = ATT_SMEM_FLOATS * sizeof(float);
    cudaFuncSetAttribute(attn_kernel,
                         cudaFuncAttributeMaxDynamicSharedMemorySize, smem_bytes);

    // Q projection: [4096,1024] @ [1024,1024]
    sgemm_kernel<0><<<dim3(DI_ / 128, (B_ * N_) / 128), 256>>>(
        seq, Wq, D_, DI_, nullptr, nullptr);
    // KV projection: [4096,1024] @ [1024,2048]
    sgemm_kernel<1><<<dim3((2 * DI_) / 128, (B_ * N_) / 128), 256>>>(
        seq, Wkv, D_, 2 * DI_, nullptr, nullptr);
    // Attention
    attn_kernel<<<dim3(N_ / 64, B_ * H_), 256, smem_bytes>>>(bias, mask);
    // Gate GEMM + fused sigmoid * attn_out
    sgemm_kernel<2><<<dim3(DI_ / 128, (B_ * N_) / 128), 256>>>(
        seq, Wg, D_, DI_, bg, nullptr);
    // Output projection
    sgemm_kernel<3><<<dim3(D_ / 128, (B_ * N_) / 128), 256>>>(
        nullptr, Wo, DI_, D_, nullptr, out);
}

// round 5
// speedup vs baseline: 2.6531x; 2.6531x over previous
#include <cuda_runtime.h>

// Problem constants
#define B_  2
#define N_  2048
#define D_  1024
#define H_  16
#define DH_ 64
#define DI_ 1024
#define SCALE_ 0.125f   // 64^-0.5

// Scratch (device globals: allocation-free per harness rules)
__device__ float g_q[B_*H_*N_*DH_];      // [b,h,n,dh], scale folded in
__device__ float g_k[B_*H_*N_*DH_];
__device__ float g_v[B_*H_*N_*DH_];
__device__ float g_att[B_*N_*DI_];       // attention out, token-major
__device__ float g_gated[B_*N_*DI_];     // gated attention out

// ---------------------------------------------------------------------------
// tf32 helpers
// ---------------------------------------------------------------------------
__device__ __forceinline__ unsigned f2tf(float x) {
    unsigned r;
    asm("cvt.rna.tf32.f32 %0, %1;" : "=r"(r) : "f"(x));
    return r;
}

__device__ __forceinline__ void mma8(float* c, const unsigned* a, const unsigned* b) {
    asm volatile(
        "mma.sync.aligned.m16n8k8.row.col.f32.tf32.tf32.f32 "
        "{%0,%1,%2,%3},{%4,%5,%6,%7},{%8,%9},{%0,%1,%2,%3};"
        : "+f"(c[0]), "+f"(c[1]), "+f"(c[2]), "+f"(c[3])
        : "r"(a[0]), "r"(a[1]), "r"(a[2]), "r"(a[3]), "r"(b[0]), "r"(b[1]));
}

// ---------------------------------------------------------------------------
// tf32 tensor-core GEMM: C[M,NN] = A[M,K] @ W[K,NN]
// 128x128 block, K-chunk 32. 8 warps as 2(M)x4(N); warp tile 64x32.
// MODE 0: Q proj  -> g_q (head split, *SCALE)
// MODE 1: KV proj -> g_k / g_v (head split)
// MODE 2: gate    -> g_gated = g_att * sigmoid(acc + bg)
// MODE 3: out     -> out = g_gated @ Wo  (reads g_gated)
// ---------------------------------------------------------------------------
template<int MODE>
__global__ void __launch_bounds__(256, 2) tgemm_kernel(
    const float* __restrict__ A, const float* __restrict__ W,
    int K, int NN, const float* __restrict__ bg, float* __restrict__ out)
{
    // As[row][k] stride 36 (bank = 4*row + k : conflict-free frag loads)
    // Bs[k][n]   stride 136 (bank = 8*k + n : conflict-free frag loads)
    __shared__ unsigned As[128 * 36];
    __shared__ unsigned Bs[32 * 136];

    const float* Aptr = (MODE == 3) ? g_gated : A;

    const int tid  = threadIdx.x;
    const int wid  = tid >> 5;
    const int lane = tid & 31;
    const int lr   = lane >> 2;   // 0..7
    const int lc   = lane & 3;    // 0..3
    const int wm   = wid >> 2;    // 0..1 (64 rows)
    const int wn   = wid & 3;     // 0..3 (32 cols)
    const int row0 = blockIdx.y * 128;
    const int col0 = blockIdx.x * 128;

    float acc[4][4][4];
    #pragma unroll
    for (int mf = 0; mf < 4; mf++)
        #pragma unroll
        for (int nf = 0; nf < 4; nf++)
            #pragma unroll
            for (int e = 0; e < 4; e++) acc[mf][nf][e] = 0.f;

    for (int k0 = 0; k0 < K; k0 += 32) {
        __syncthreads();   // previous chunk's compute done
        // Load A chunk: 128 x 32
        #pragma unroll
        for (int it = 0; it < 4; it++) {
            const int i = tid + it * 256;
            const int r = i >> 3, c4 = (i & 7) * 4;
            float4 v = *(const float4*)&Aptr[(size_t)(row0 + r) * K + k0 + c4];
            uint4 u = make_uint4(f2tf(v.x), f2tf(v.y), f2tf(v.z), f2tf(v.w));
            *(uint4*)&As[r * 36 + c4] = u;
        }
        // Load B chunk: 32 x 128
        #pragma unroll
        for (int it = 0; it < 4; it++) {
            const int i = tid + it * 256;
            const int r = i >> 5, c4 = (i & 31) * 4;
            float4 v = *(const float4*)&W[(size_t)(k0 + r) * NN + col0 + c4];
            uint4 u = make_uint4(f2tf(v.x), f2tf(v.y), f2tf(v.z), f2tf(v.w));
            *(uint4*)&Bs[r * 136 + c4] = u;
        }
        __syncthreads();

        #pragma unroll
        for (int ks = 0; ks < 4; ks++) {
            unsigned a[4][4], b[4][2];
            #pragma unroll
            for (int mf = 0; mf < 4; mf++) {
                const unsigned* p = &As[(wm * 64 + mf * 16 + lr) * 36 + ks * 8 + lc];
                a[mf][0] = p[0]; a[mf][1] = p[288]; a[mf][2] = p[4]; a[mf][3] = p[292];
            }
            #pragma unroll
            for (int nf = 0; nf < 4; nf++) {
                const unsigned* p = &Bs[(ks * 8 + lc) * 136 + wn * 32 + nf * 8 + lr];
                b[nf][0] = p[0]; b[nf][1] = p[544];
            }
            #pragma unroll
            for (int mf = 0; mf < 4; mf++)
                #pragma unroll
                for (int nf = 0; nf < 4; nf++)
                    mma8(acc[mf][nf], a[mf], b[nf]);
        }
    }

    // Epilogue (float2 granularity: c0/c1 and c2/c3 are adjacent columns)
    #pragma unroll
    for (int mf = 0; mf < 4; mf++) {
        #pragma unroll
        for (int hf = 0; hf < 2; hf++) {
            const int m  = row0 + wm * 64 + mf * 16 + lr + hf * 8;
            const int bb = m >> 11;
            const int ii = m & 2047;
            #pragma unroll
            for (int nf = 0; nf < 4; nf++) {
                const int col = col0 + wn * 32 + nf * 8 + 2 * lc;
                float2 v = make_float2(acc[mf][nf][hf * 2], acc[mf][nf][hf * 2 + 1]);
                if (MODE == 0) {
                    v.x *= SCALE_; v.y *= SCALE_;
                    const int hh = col >> 6, dd = col & 63;
                    *(float2*)&g_q[(((size_t)(bb * H_ + hh)) * N_ + ii) * DH_ + dd] = v;
                } else if (MODE == 1) {
                    if (col < DI_) {
                        const int hh = col >> 6, dd = col & 63;
                        *(float2*)&g_k[(((size_t)(bb * H_ + hh)) * N_ + ii) * DH_ + dd] = v;
                    } else {
                        const int c = col - DI_;
                        const int hh = c >> 6, dd = c & 63;
                        *(float2*)&g_v[(((size_t)(bb * H_ + hh)) * N_ + ii) * DH_ + dd] = v;
                    }
                } else if (MODE == 2) {
                    const size_t idx = (size_t)m * DI_ + col;
                    float2 ao  = *(const float2*)&g_att[idx];
                    float2 bgv = *(const float2*)&bg[col];
                    v.x = ao.x / (1.f + __expf(-(v.x + bgv.x)));
                    v.y = ao.y / (1.f + __expf(-(v.y + bgv.y)));
                    *(float2*)&g_gated[idx] = v;
                } else {
                    *(float2*)&out[(size_t)m * D_ + col] = v;
                }
            }
        }
    }
}

// ---------------------------------------------------------------------------
// Flash attention, tf32 tensor cores.
// Block = 128 q-rows of one (b,h); 8 warps, each owns 16 q-rows x FULL j-tile
// => softmax is warp-local (no cross-warp reductions).
// j-tile = 64. S accumulators initialized with bias+mask (mma adds on top).
// ---------------------------------------------------------------------------
#define AQ (128 * 68)
#define AK (64 * 68)
#define AV (64 * 72)
#define AP (128 * 68)
#define ATT_SMEM_BYTES ((AQ + AK + AV + AP + 64) * 4)

__global__ void __launch_bounds__(256, 2) fattn_kernel(
    const float* __restrict__ bias, const int* __restrict__ mask)
{
    extern __shared__ unsigned sm[];
    unsigned* Qs = sm;            // [q][d]  stride 68 (tf32 bits)
    unsigned* Ks = Qs + AQ;       // [j][d]  stride 68
    unsigned* Vs = Ks + AK;       // [j][d]  stride 72
    unsigned* Ps = Vs + AV;       // [q][j]  stride 68 (warp-private rows)
    float* msk   = (float*)(Ps + AP);   // [64] additive mask

    const int tid  = threadIdx.x;
    const int wid  = tid >> 5;
    const int lane = tid & 31;
    const int lr   = lane >> 2;
    const int lc   = lane & 3;
    const int bh   = blockIdx.y;
    const int b    = bh >> 4;
    const int h    = bh & 15;
    const int i0   = blockIdx.x * 128;
    const int q0   = wid * 16;        // warp's local q base

    const float* qbase = g_q + ((size_t)bh * N_ + i0) * DH_;
    const float* kbase = g_k + (size_t)bh * N_ * DH_;
    const float* vbase = g_v + (size_t)bh * N_ * DH_;
    const float* bp0 = bias + ((size_t)bh * N_ + i0 + q0 + lr) * N_;
    const float* bp1 = bp0 + 8 * (size_t)N_;

    // Load Q tile once (cvt to tf32 at store)
    #pragma unroll
    for (int it = 0; it < 8; it++) {
        const int i = tid + it * 256;
        const int r = i >> 4, c4 = (i & 15) * 4;
        float4 v = *(const float4*)&qbase[(size_t)r * DH_ + c4];
        uint4 u = make_uint4(f2tf(v.x), f2tf(v.y), f2tf(v.z), f2tf(v.w));
        *(uint4*)&Qs[r * 68 + c4] = u;
    }

    float S[8][4], O[8][4];
    float mi0 = -1e30f, mi1 = -1e30f, li0 = 0.f, li1 = 0.f;
    #pragma unroll
    for (int nf = 0; nf < 8; nf++) {
        O[nf][0] = O[nf][1] = O[nf][2] = O[nf][3] = 0.f;
    }

    for (int t = 0; t < N_ / 64; t++) {
        const int j0 = t * 64;
        __syncthreads();   // all warps done with previous K/V tiles
        #pragma unroll
        for (int it = 0; it < 4; it++) {
            const int i = tid + it * 256;
            const int r = i >> 4, c4 = (i & 15) * 4;
            float4 kv = *(const float4*)&kbase[(size_t)(j0 + r) * DH_ + c4];
            uint4 uk = make_uint4(f2tf(kv.x), f2tf(kv.y), f2tf(kv.z), f2tf(kv.w));
            *(uint4*)&Ks[r * 68 + c4] = uk;
            float4 vv = *(const float4*)&vbase[(size_t)(j0 + r) * DH_ + c4];
            uint4 uv = make_uint4(f2tf(vv.x), f2tf(vv.y), f2tf(vv.z), f2tf(vv.w));
            *(uint4*)&Vs[r * 72 + c4] = uv;
        }
        if (tid < 64)
            msk[tid] = (mask[(size_t)b * N_ + j0 + tid] != 0) ? 0.f : -1e30f;
        __syncthreads();

        // Init S with bias + mask; mma accumulates Q.K^T on top.
        #pragma unroll
        for (int nf = 0; nf < 8; nf++) {
            const int jc = nf * 8 + 2 * lc;
            float2 b0 = *(const float2*)&bp0[j0 + jc];
            float2 b1 = *(const float2*)&bp1[j0 + jc];
            float2 mm = *(const float2*)&msk[jc];
            S[nf][0] = b0.x + mm.x; S[nf][1] = b0.y + mm.y;
            S[nf][2] = b1.x + mm.x; S[nf][3] = b1.y + mm.y;
        }

        // S += Q @ K^T
        #pragma unroll
        for (int ks = 0; ks < 8; ks++) {
            unsigned a[4];
            const unsigned* pa = &Qs[(q0 + lr) * 68 + ks * 8 + lc];
            a[0] = pa[0]; a[1] = pa[544]; a[2] = pa[4]; a[3] = pa[548];
            #pragma unroll
            for (int nf = 0; nf < 8; nf++) {
                unsigned bf[2];
                const unsigned* pb = &Ks[(nf * 8 + lr) * 68 + ks * 8 + lc];
                bf[0] = pb[0]; bf[1] = pb[4];
                mma8(S[nf], a, bf);
            }
        }

        // Row max (rows lr and lr+8), warp-local
        float m0 = -1e30f, m1 = -1e30f;
        #pragma unroll
        for (int nf = 0; nf < 8; nf++) {
            m0 = fmaxf(m0, fmaxf(S[nf][0], S[nf][1]));
            m1 = fmaxf(m1, fmaxf(S[nf][2], S[nf][3]));
        }
        m0 = fmaxf(m0, __shfl_xor_sync(~0u, m0, 1));
        m0 = fmaxf(m0, __shfl_xor_sync(~0u, m0, 2));
        m1 = fmaxf(m1, __shfl_xor_sync(~0u, m1, 1));
        m1 = fmaxf(m1, __shfl_xor_sync(~0u, m1, 2));

        const float mn0 = fmaxf(mi0, m0), mn1 = fmaxf(mi1, m1);
        const float cr0 = __expf(mi0 - mn0), cr1 = __expf(mi1 - mn1);
        mi0 = mn0; mi1 = mn1;

        float s0 = 0.f, s1 = 0.f;
        #pragma unroll
        for (int nf = 0; nf < 8; nf++) {
            S[nf][0] = __expf(S[nf][0] - mn0);
            S[nf][1] = __expf(S[nf][1] - mn0);
            S[nf][2] = __expf(S[nf][2] - mn1);
            S[nf][3] = __expf(S[nf][3] - mn1);
            s0 += S[nf][0] + S[nf][1];
            s1 += S[nf][2] + S[nf][3];
            O[nf][0] *= cr0; O[nf][1] *= cr0;
            O[nf][2] *= cr1; O[nf][3] *= cr1;
            uint2 u0 = make_uint2(f2tf(S[nf][0]), f2tf(S[nf][1]));
            *(uint2*)&Ps[(q0 + lr) * 68 + nf * 8 + 2 * lc] = u0;
            uint2 u1 = make_uint2(f2tf(S[nf][2]), f2tf(S[nf][3]));
            *(uint2*)&Ps[(q0 + lr + 8) * 68 + nf * 8 + 2 * lc] = u1;
        }
        s0 += __shfl_xor_sync(~0u, s0, 1);
        s0 += __shfl_xor_sync(~0u, s0, 2);
        s1 += __shfl_xor_sync(~0u, s1, 1);
        s1 += __shfl_xor_sync(~0u, s1, 2);
        li0 = li0 * cr0 + s0;
        li1 = li1 * cr1 + s1;

        __syncwarp();   // Ps stores visible across lanes within the warp

        // O += P @ V  (P rows are warp-private)
        #pragma unroll
        for (int ks = 0; ks < 8; ks++) {
            unsigned a[4];
            const unsigned* pa = &Ps[(q0 + lr) * 68 + ks * 8 + lc];
            a[0] = pa[0]; a[1] = pa[544]; a[2] = pa[4]; a[3] = pa[548];
            #pragma unroll
            for (int nf = 0; nf < 8; nf++) {
                unsigned bf[2];
                const unsigned* pb = &Vs[(ks * 8 + lc) * 72 + nf * 8 + lr];
                bf[0] = pb[0]; bf[1] = pb[288];
                mma8(O[nf], a, bf);
            }
        }
    }

    // Normalize + write token-major [b, i, h*64 + d]
    const float inv0 = 1.f / li0, inv1 = 1.f / li1;
    const size_t r0 = ((size_t)b * N_ + i0 + q0 + lr) * DI_ + h * DH_;
    const size_t r1 = r0 + 8 * (size_t)DI_;
    #pragma unroll
    for (int nf = 0; nf < 8; nf++) {
        const int dd = nf * 8 + 2 * lc;
        float2 v0 = make_float2(O[nf][0] * inv0, O[nf][1] * inv0);
        *(float2*)&g_att[r0 + dd] = v0;
        float2 v1 = make_float2(O[nf][2] * inv1, O[nf][3] * inv1);
        *(float2*)&g_att[r1 + dd] = v1;
    }
}

// ---------------------------------------------------------------------------
extern "C" void kernel_launch(void* const* d_in, const int* in_sizes, int n_in,
                              void* d_out, int out_size)
{
    const float* seq  = (const float*)d_in[0];
    const int*   mask = (const int*)d_in[1];
    const float* bias = (const float*)d_in[2];
    const float* Wq   = (const float*)d_in[3];
    const float* Wkv  = (const float*)d_in[4];
    const float* Wo   = (const float*)d_in[5];
    const float* Wg   = (const float*)d_in[6];
    const float* bg   = (const float*)d_in[7];
    float* out = (float*)d_out;

    cudaFuncSetAttribute(fattn_kernel,
                         cudaFuncAttributeMaxDynamicSharedMemorySize,
                         ATT_SMEM_BYTES);

    // Q projection: [4096,1024] @ [1024,1024]
    tgemm_kernel<0><<<dim3(DI_ / 128, (B_ * N_) / 128), 256>>>(
        seq, Wq, D_, DI_, nullptr, nullptr);
    // KV projection: [4096,1024] @ [1024,2048]
    tgemm_kernel<1><<<dim3((2 * DI_) / 128, (B_ * N_) / 128), 256>>>(
        seq, Wkv, D_, 2 * DI_, nullptr, nullptr);
    // Attention
    fattn_kernel<<<dim3(N_ / 128, B_ * H_), 256, ATT_SMEM_BYTES>>>(bias, mask);
    // Gate GEMM + fused sigmoid * attn_out
    tgemm_kernel<2><<<dim3(DI_ / 128, (B_ * N_) / 128), 256>>>(
        seq, Wg, D_, DI_, bg, nullptr);
    // Output projection
    tgemm_kernel<3><<<dim3(D_ / 128, (B_ * N_) / 128), 256>>>(
        nullptr, Wo, DI_, D_, nullptr, out);
}

// round 6
// speedup vs baseline: 2.8239x; 1.0644x over previous
#include <cuda_runtime.h>

// Problem constants
#define B_  2
#define N_  2048
#define D_  1024
#define H_  16
#define DH_ 64
#define DI_ 1024
#define SCALE_ 0.125f   // 64^-0.5

// Scratch (device globals: allocation-free per harness rules)
__device__ float g_q[B_*H_*N_*DH_];
__device__ float g_k[B_*H_*N_*DH_];
__device__ float g_v[B_*H_*N_*DH_];
__device__ float g_att[B_*N_*DI_];
__device__ float g_gated[B_*N_*DI_];

// ---------------------------------------------------------------------------
// helpers
// ---------------------------------------------------------------------------
__device__ __forceinline__ unsigned f2tf(float x) {
    unsigned r;
    asm("cvt.rna.tf32.f32 %0, %1;" : "=r"(r) : "f"(x));
    return r;
}

__device__ __forceinline__ void mma8(float* c, const unsigned* a, const unsigned* b) {
    asm volatile(
        "mma.sync.aligned.m16n8k8.row.col.f32.tf32.tf32.f32 "
        "{%0,%1,%2,%3},{%4,%5,%6,%7},{%8,%9},{%0,%1,%2,%3};"
        : "+f"(c[0]), "+f"(c[1]), "+f"(c[2]), "+f"(c[3])
        : "r"(a[0]), "r"(a[1]), "r"(a[2]), "r"(a[3]), "r"(b[0]), "r"(b[1]));
}

__device__ __forceinline__ unsigned sptr(const void* p) {
    return (unsigned)__cvta_generic_to_shared(p);
}
#define CP16(dst, src) \
    asm volatile("cp.async.cg.shared.global [%0], [%1], 16;" :: "r"(dst), "l"(src))
#define CP_COMMIT() asm volatile("cp.async.commit_group;" ::: "memory")
#define CP_WAIT(n)  asm volatile("cp.async.wait_group %0;" :: "n"(n) : "memory")

// ---------------------------------------------------------------------------
// tf32 tensor-core GEMM, cp.async double-buffered.
// C[M,NN] = A[M,K] @ W[K,NN]; 128x128 block, K-chunk 32; 8 warps 2(M)x4(N).
// Raw f32 in smem; cvt.rna.tf32 at fragment load (same numerics as before).
// MODE 0: Q proj -> g_q (*SCALE, head split)
// MODE 1: KV proj -> g_k/g_v (head split)
// MODE 2: gate -> g_gated = g_att * sigmoid(acc + bg)
// MODE 3: out -> out = g_gated @ Wo
// ---------------------------------------------------------------------------
#define GA 4608   // 128*36 floats per A buffer
#define GB 4352   // 32*136 floats per B buffer
#define GEMM_SMEM_BYTES ((2*GA + 2*GB) * 4)

template<int MODE>
__global__ void __launch_bounds__(256, 2) tgemm_kernel(
    const float* __restrict__ A, const float* __restrict__ W,
    int K, int NN, const float* __restrict__ bg, float* __restrict__ out)
{
    extern __shared__ float smf[];
    float* As = smf;             // [2][128*36], bank = 4*row + k
    float* Bs = smf + 2 * GA;    // [2][32*136], bank = 8*k + n

    const float* Aptr = (MODE == 3) ? g_gated : A;

    const int tid  = threadIdx.x;
    const int wid  = tid >> 5;
    const int lane = tid & 31;
    const int lr   = lane >> 2;
    const int lc   = lane & 3;
    const int wm   = wid >> 2;
    const int wn   = wid & 3;
    const int row0 = blockIdx.y * 128;
    const int col0 = blockIdx.x * 128;

    // Per-thread load coords
    const int ar = tid >> 3, ac = (tid & 7) * 4;        // A: 128x32, 2 iters? no: 4 iters of 256 threads covers 1024 float4 -> use it loop
    const int br = tid >> 5, bc = (tid & 31) * 4;

    float acc[4][4][4];
    #pragma unroll
    for (int mf = 0; mf < 4; mf++)
        #pragma unroll
        for (int nf = 0; nf < 4; nf++)
            #pragma unroll
            for (int e = 0; e < 4; e++) acc[mf][nf][e] = 0.f;

    auto loadChunk = [&](int k0, int buf) {
        float* Ad = As + buf * GA;
        float* Bd = Bs + buf * GB;
        #pragma unroll
        for (int it = 0; it < 4; it++) {
            const int r = ar + it * 32;                  // rows 0..127
            CP16(sptr(&Ad[r * 36 + ac]),
                 &Aptr[(size_t)(row0 + r) * K + k0 + ac]);
        }
        #pragma unroll
        for (int it = 0; it < 4; it++) {
            const int r = br + it * 8;                   // k rows 0..31
            CP16(sptr(&Bd[r * 136 + bc]),
                 &W[(size_t)(k0 + r) * NN + col0 + bc]);
        }
        CP_COMMIT();
    };

    loadChunk(0, 0);
    const int nch = K >> 5;
    for (int ch = 0; ch < nch; ch++) {
        const int cur = ch & 1;
        __syncthreads();                  // all warps done computing buf cur^1
        if (ch + 1 < nch) {
            loadChunk((ch + 1) * 32, cur ^ 1);
            CP_WAIT(1);                   // cur done; next stays in flight
        } else {
            CP_WAIT(0);
        }
        __syncthreads();

        const float* Ab = As + cur * GA;
        const float* Bb = Bs + cur * GB;
        #pragma unroll
        for (int ks = 0; ks < 4; ks++) {
            unsigned a[4][4], b[4][2];
            #pragma unroll
            for (int mf = 0; mf < 4; mf++) {
                const float* p = &Ab[(wm * 64 + mf * 16 + lr) * 36 + ks * 8 + lc];
                a[mf][0] = f2tf(p[0]);   a[mf][1] = f2tf(p[288]);
                a[mf][2] = f2tf(p[4]);   a[mf][3] = f2tf(p[292]);
            }
            #pragma unroll
            for (int nf = 0; nf < 4; nf++) {
                const float* p = &Bb[(ks * 8 + lc) * 136 + wn * 32 + nf * 8 + lr];
                b[nf][0] = f2tf(p[0]);   b[nf][1] = f2tf(p[544]);
            }
            #pragma unroll
            for (int mf = 0; mf < 4; mf++)
                #pragma unroll
                for (int nf = 0; nf < 4; nf++)
                    mma8(acc[mf][nf], a[mf], b[nf]);
        }
    }

    // Epilogue
    #pragma unroll
    for (int mf = 0; mf < 4; mf++) {
        #pragma unroll
        for (int hf = 0; hf < 2; hf++) {
            const int m  = row0 + wm * 64 + mf * 16 + lr + hf * 8;
            const int bb = m >> 11;
            const int ii = m & 2047;
            #pragma unroll
            for (int nf = 0; nf < 4; nf++) {
                const int col = col0 + wn * 32 + nf * 8 + 2 * lc;
                float2 v = make_float2(acc[mf][nf][hf * 2], acc[mf][nf][hf * 2 + 1]);
                if (MODE == 0) {
                    v.x *= SCALE_; v.y *= SCALE_;
                    const int hh = col >> 6, dd = col & 63;
                    *(float2*)&g_q[(((size_t)(bb * H_ + hh)) * N_ + ii) * DH_ + dd] = v;
                } else if (MODE == 1) {
                    if (col < DI_) {
                        const int hh = col >> 6, dd = col & 63;
                        *(float2*)&g_k[(((size_t)(bb * H_ + hh)) * N_ + ii) * DH_ + dd] = v;
                    } else {
                        const int c = col - DI_;
                        const int hh = c >> 6, dd = c & 63;
                        *(float2*)&g_v[(((size_t)(bb * H_ + hh)) * N_ + ii) * DH_ + dd] = v;
                    }
                } else if (MODE == 2) {
                    const size_t idx = (size_t)m * DI_ + col;
                    float2 ao  = *(const float2*)&g_att[idx];
                    float2 bgv = *(const float2*)&bg[col];
                    v.x = ao.x / (1.f + __expf(-(v.x + bgv.x)));
                    v.y = ao.y / (1.f + __expf(-(v.y + bgv.y)));
                    *(float2*)&g_gated[idx] = v;
                } else {
                    *(float2*)&out[(size_t)m * D_ + col] = v;
                }
            }
        }
    }
}

// ---------------------------------------------------------------------------
// Flash attention, tf32 tensor cores.
// Block = 128 q-rows of one (b,h); 8 warps each own 16 q-rows x full 64 j-tile
// (softmax warp-local). Bias+mask preloaded into regs BEFORE the QK mma loop
// (S zero-init) so the DRAM latency hides under 64 mmas; added afterwards.
// ---------------------------------------------------------------------------
#define AQ (128 * 68)
#define AK (64 * 68)
#define AV (64 * 72)
#define AP (128 * 68)
#define ATT_SMEM_BYTES ((AQ + AK + AV + AP + 64) * 4)

__global__ void __launch_bounds__(256, 2) fattn_kernel(
    const float* __restrict__ bias, const int* __restrict__ mask)
{
    extern __shared__ unsigned sm[];
    unsigned* Qs = sm;            // [q][d]  stride 68 (tf32 bits)
    unsigned* Ks = Qs + AQ;       // [j][d]  stride 68
    unsigned* Vs = Ks + AK;       // [j][d]  stride 72
    unsigned* Ps = Vs + AV;       // [q][j]  stride 68 (warp-private rows)
    float* msk   = (float*)(Ps + AP);

    const int tid  = threadIdx.x;
    const int wid  = tid >> 5;
    const int lane = tid & 31;
    const int lr   = lane >> 2;
    const int lc   = lane & 3;
    const int bh   = blockIdx.y;
    const int b    = bh >> 4;
    const int h    = bh & 15;
    const int i0   = blockIdx.x * 128;
    const int q0   = wid * 16;

    const float* qbase = g_q + ((size_t)bh * N_ + i0) * DH_;
    const float* kbase = g_k + (size_t)bh * N_ * DH_;
    const float* vbase = g_v + (size_t)bh * N_ * DH_;
    const float* bp0 = bias + ((size_t)bh * N_ + i0 + q0 + lr) * N_;
    const float* bp1 = bp0 + 8 * (size_t)N_;

    // Load Q tile once (cvt to tf32 at store)
    #pragma unroll
    for (int it = 0; it < 8; it++) {
        const int i = tid + it * 256;
        const int r = i >> 4, c4 = (i & 15) * 4;
        float4 v = *(const float4*)&qbase[(size_t)r * DH_ + c4];
        uint4 u = make_uint4(f2tf(v.x), f2tf(v.y), f2tf(v.z), f2tf(v.w));
        *(uint4*)&Qs[r * 68 + c4] = u;
    }

    float S[8][4], O[8][4];
    float mi0 = -1e30f, mi1 = -1e30f, li0 = 0.f, li1 = 0.f;
    #pragma unroll
    for (int nf = 0; nf < 8; nf++)
        O[nf][0] = O[nf][1] = O[nf][2] = O[nf][3] = 0.f;

    for (int t = 0; t < N_ / 64; t++) {
        const int j0 = t * 64;
        __syncthreads();
        #pragma unroll
        for (int it = 0; it < 4; it++) {
            const int i = tid + it * 256;
            const int r = i >> 4, c4 = (i & 15) * 4;
            float4 kv = *(const float4*)&kbase[(size_t)(j0 + r) * DH_ + c4];
            uint4 uk = make_uint4(f2tf(kv.x), f2tf(kv.y), f2tf(kv.z), f2tf(kv.w));
            *(uint4*)&Ks[r * 68 + c4] = uk;
            float4 vv = *(const float4*)&vbase[(size_t)(j0 + r) * DH_ + c4];
            uint4 uv = make_uint4(f2tf(vv.x), f2tf(vv.y), f2tf(vv.z), f2tf(vv.w));
            *(uint4*)&Vs[r * 72 + c4] = uv;
        }
        if (tid < 64)
            msk[tid] = (mask[(size_t)b * N_ + j0 + tid] != 0) ? 0.f : -1e30f;
        __syncthreads();

        // Preload bias (+mask folded) — these LDGs fly under the mma loop.
        float2 bA[8], bB[8];
        #pragma unroll
        for (int nf = 0; nf < 8; nf++) {
            const int jc = nf * 8 + 2 * lc;
            float2 mm = *(const float2*)&msk[jc];
            float2 t0 = *(const float2*)&bp0[j0 + jc];
            float2 t1 = *(const float2*)&bp1[j0 + jc];
            bA[nf].x = t0.x + mm.x; bA[nf].y = t0.y + mm.y;
            bB[nf].x = t1.x + mm.x; bB[nf].y = t1.y + mm.y;
        }

        // S = Q @ K^T (zero-init)
        #pragma unroll
        for (int nf = 0; nf < 8; nf++)
            S[nf][0] = S[nf][1] = S[nf][2] = S[nf][3] = 0.f;
        #pragma unroll
        for (int ks = 0; ks < 8; ks++) {
            unsigned a[4];
            const unsigned* pa = &Qs[(q0 + lr) * 68 + ks * 8 + lc];
            a[0] = pa[0]; a[1] = pa[544]; a[2] = pa[4]; a[3] = pa[548];
            #pragma unroll
            for (int nf = 0; nf < 8; nf++) {
                unsigned bf[2];
                const unsigned* pb = &Ks[(nf * 8 + lr) * 68 + ks * 8 + lc];
                bf[0] = pb[0]; bf[1] = pb[4];
                mma8(S[nf], a, bf);
            }
        }

        // Add bias+mask
        #pragma unroll
        for (int nf = 0; nf < 8; nf++) {
            S[nf][0] += bA[nf].x; S[nf][1] += bA[nf].y;
            S[nf][2] += bB[nf].x; S[nf][3] += bB[nf].y;
        }

        // Warp-local row max
        float m0 = -1e30f, m1 = -1e30f;
        #pragma unroll
        for (int nf = 0; nf < 8; nf++) {
            m0 = fmaxf(m0, fmaxf(S[nf][0], S[nf][1]));
            m1 = fmaxf(m1, fmaxf(S[nf][2], S[nf][3]));
        }
        m0 = fmaxf(m0, __shfl_xor_sync(~0u, m0, 1));
        m0 = fmaxf(m0, __shfl_xor_sync(~0u, m0, 2));
        m1 = fmaxf(m1, __shfl_xor_sync(~0u, m1, 1));
        m1 = fmaxf(m1, __shfl_xor_sync(~0u, m1, 2));

        const float mn0 = fmaxf(mi0, m0), mn1 = fmaxf(mi1, m1);
        const float cr0 = __expf(mi0 - mn0), cr1 = __expf(mi1 - mn1);
        mi0 = mn0; mi1 = mn1;

        float s0 = 0.f, s1 = 0.f;
        #pragma unroll
        for (int nf = 0; nf < 8; nf++) {
            S[nf][0] = __expf(S[nf][0] - mn0);
            S[nf][1] = __expf(S[nf][1] - mn0);
            S[nf][2] = __expf(S[nf][2] - mn1);
            S[nf][3] = __expf(S[nf][3] - mn1);
            s0 += S[nf][0] + S[nf][1];
            s1 += S[nf][2] + S[nf][3];
            O[nf][0] *= cr0; O[nf][1] *= cr0;
            O[nf][2] *= cr1; O[nf][3] *= cr1;
            uint2 u0 = make_uint2(f2tf(S[nf][0]), f2tf(S[nf][1]));
            *(uint2*)&Ps[(q0 + lr) * 68 + nf * 8 + 2 * lc] = u0;
            uint2 u1 = make_uint2(f2tf(S[nf][2]), f2tf(S[nf][3]));
            *(uint2*)&Ps[(q0 + lr + 8) * 68 + nf * 8 + 2 * lc] = u1;
        }
        s0 += __shfl_xor_sync(~0u, s0, 1);
        s0 += __shfl_xor_sync(~0u, s0, 2);
        s1 += __shfl_xor_sync(~0u, s1, 1);
        s1 += __shfl_xor_sync(~0u, s1, 2);
        li0 = li0 * cr0 + s0;
        li1 = li1 * cr1 + s1;

        __syncwarp();

        // O += P @ V
        #pragma unroll
        for (int ks = 0; ks < 8; ks++) {
            unsigned a[4];
            const unsigned* pa = &Ps[(q0 + lr) * 68 + ks * 8 + lc];
            a[0] = pa[0]; a[1] = pa[544]; a[2] = pa[4]; a[3] = pa[548];
            #pragma unroll
            for (int nf = 0; nf < 8; nf++) {
                unsigned bf[2];
                const unsigned* pb = &Vs[(ks * 8 + lc) * 72 + nf * 8 + lr];
                bf[0] = pb[0]; bf[1] = pb[288];
                mma8(O[nf], a, bf);
            }
        }
    }

    // Normalize + write token-major [b, i, h*64 + d]
    const float inv0 = 1.f / li0, inv1 = 1.f / li1;
    const size_t r0 = ((size_t)b * N_ + i0 + q0 + lr) * DI_ + h * DH_;
    const size_t r1 = r0 + 8 * (size_t)DI_;
    #pragma unroll
    for (int nf = 0; nf < 8; nf++) {
        const int dd = nf * 8 + 2 * lc;
        *(float2*)&g_att[r0 + dd] = make_float2(O[nf][0] * inv0, O[nf][1] * inv0);
        *(float2*)&g_att[r1 + dd] = make_float2(O[nf][2] * inv1, O[nf][3] * inv1);
    }
}

// ---------------------------------------------------------------------------
extern "C" void kernel_launch(void* const* d_in, const int* in_sizes, int n_in,
                              void* d_out, int out_size)
{
    const float* seq  = (const float*)d_in[0];
    const int*   mask = (const int*)d_in[1];
    const float* bias = (const float*)d_in[2];
    const float* Wq   = (const float*)d_in[3];
    const float* Wkv  = (const float*)d_in[4];
    const float* Wo   = (const float*)d_in[5];
    const float* Wg   = (const float*)d_in[6];
    const float* bg   = (const float*)d_in[7];
    float* out = (float*)d_out;

    cudaFuncSetAttribute(tgemm_kernel<0>,
        cudaFuncAttributeMaxDynamicSharedMemorySize, GEMM_SMEM_BYTES);
    cudaFuncSetAttribute(tgemm_kernel<1>,
        cudaFuncAttributeMaxDynamicSharedMemorySize, GEMM_SMEM_BYTES);
    cudaFuncSetAttribute(tgemm_kernel<2>,
        cudaFuncAttributeMaxDynamicSharedMemorySize, GEMM_SMEM_BYTES);
    cudaFuncSetAttribute(tgemm_kernel<3>,
        cudaFuncAttributeMaxDynamicSharedMemorySize, GEMM_SMEM_BYTES);
    cudaFuncSetAttribute(fattn_kernel,
        cudaFuncAttributeMaxDynamicSharedMemorySize, ATT_SMEM_BYTES);

    tgemm_kernel<0><<<dim3(DI_ / 128, (B_ * N_) / 128), 256, GEMM_SMEM_BYTES>>>(
        seq, Wq, D_, DI_, nullptr, nullptr);
    tgemm_kernel<1><<<dim3((2 * DI_) / 128, (B_ * N_) / 128), 256, GEMM_SMEM_BYTES>>>(
        seq, Wkv, D_, 2 * DI_, nullptr, nullptr);
    fattn_kernel<<<dim3(N_ / 128, B_ * H_), 256, ATT_SMEM_BYTES>>>(bias, mask);
    tgemm_kernel<2><<<dim3(DI_ / 128, (B_ * N_) / 128), 256, GEMM_SMEM_BYTES>>>(
        seq, Wg, D_, DI_, bg, nullptr);
    tgemm_kernel<3><<<dim3(D_ / 128, (B_ * N_) / 128), 256, GEMM_SMEM_BYTES>>>(
        nullptr, Wo, DI_, D_, nullptr, out);
}

// round 8
// speedup vs baseline: 2.9329x; 1.0386x over previous
#include <cuda_runtime.h>

// Problem constants
#define B_  2
#define N_  2048
#define D_  1024
#define H_  16
#define DH_ 64
#define DI_ 1024
#define SCALE_ 0.125f   // 64^-0.5 (exact power of 2: tf32-exactness preserved)

// Scratch (device globals: allocation-free per harness rules)
__device__ float g_q[B_*H_*N_*DH_];      // tf32-exact
__device__ float g_k[B_*H_*N_*DH_];      // tf32-exact
__device__ float g_v[B_*H_*N_*DH_];      // tf32-exact
__device__ float g_att[B_*N_*DI_];       // full f32
__device__ float g_gated[B_*N_*DI_];     // tf32-exact
// tf32-rounded copies of inputs (prepass)
__device__ float g_seq[B_*N_*D_];
__device__ float g_wq [D_*DI_];
__device__ float g_wkv[D_*2*DI_];
__device__ float g_wg [D_*DI_];
__device__ float g_wo [DI_*D_];

// ---------------------------------------------------------------------------
// helpers
// ---------------------------------------------------------------------------
__device__ __forceinline__ unsigned f2tf(float x) {
    unsigned r;
    asm("cvt.rna.tf32.f32 %0, %1;" : "=r"(r) : "f"(x));
    return r;
}
__device__ __forceinline__ float f2tff(float x) {
    return __uint_as_float(f2tf(x));
}

__device__ __forceinline__ void mma8(float* c, const unsigned* a, const unsigned* b) {
    asm volatile(
        "mma.sync.aligned.m16n8k8.row.col.f32.tf32.tf32.f32 "
        "{%0,%1,%2,%3},{%4,%5,%6,%7},{%8,%9},{%0,%1,%2,%3};"
        : "+f"(c[0]), "+f"(c[1]), "+f"(c[2]), "+f"(c[3])
        : "r"(a[0]), "r"(a[1]), "r"(a[2]), "r"(a[3]), "r"(b[0]), "r"(b[1]));
}

__device__ __forceinline__ unsigned sptr(const void* p) {
    return (unsigned)__cvta_generic_to_shared(p);
}
#define CP16(dst, src) \
    asm volatile("cp.async.cg.shared.global [%0], [%1], 16;" :: "r"(dst), "l"(src))
#define CP_COMMIT() asm volatile("cp.async.commit_group;" ::: "memory")
#define CP_WAIT(n)  asm volatile("cp.async.wait_group %0;" :: "n"(n) : "memory")

// ---------------------------------------------------------------------------
// Prepass: round f32 -> tf32-exact f32 (grid-stride float4)
// ---------------------------------------------------------------------------
__global__ void round_tf32_kernel(const float4* __restrict__ src,
                                  float4* __restrict__ dst, int n4)
{
    for (int i = blockIdx.x * blockDim.x + threadIdx.x; i < n4;
         i += gridDim.x * blockDim.x) {
        float4 v = src[i];
        v.x = f2tff(v.x); v.y = f2tff(v.y); v.z = f2tff(v.z); v.w = f2tff(v.w);
        dst[i] = v;
    }
}

// ---------------------------------------------------------------------------
// tf32 tensor-core GEMM, 3-stage cp.async pipeline.
// Inputs are tf32-exact f32: raw bits feed mma (zero CVTs in inner loop).
// C[M,NN] = A[M,K] @ W[K,NN]; 128x128 block, K-chunk 32; 8 warps 2(M)x4(N).
// MODE 0: Q proj -> g_q (*SCALE, head split, tf32-rounded)
// MODE 1: KV proj -> g_k/g_v (head split, tf32-rounded)
// MODE 2: gate -> g_gated = round_tf32(g_att * sigmoid(acc + bg))
// MODE 3: out -> out = g_gated @ Wo (plain f32 store)
// ---------------------------------------------------------------------------
#define GA 4608   // 128*36 words per A buffer (bank = 4*row + k)
#define GB 4352   // 32*136 words per B buffer (bank = 8*k + n)
#define GSTAGES 3
#define GEMM_SMEM_BYTES (GSTAGES * (GA + GB) * 4)

template<int MODE>
__global__ void __launch_bounds__(256, 2) tgemm_kernel(
    const float* __restrict__ A, const float* __restrict__ W,
    int K, int NN, const float* __restrict__ bg, float* __restrict__ out)
{
    extern __shared__ unsigned smu[];

    const int tid  = threadIdx.x;
    const int wid  = tid >> 5;
    const int lane = tid & 31;
    const int lr   = lane >> 2;
    const int lc   = lane & 3;
    const int wm   = wid >> 2;
    const int wn   = wid & 3;
    const int row0 = blockIdx.y * 128;
    const int col0 = blockIdx.x * 128;

    const int ar = tid >> 3, ac = (tid & 7) * 4;
    const int br = tid >> 5, bc = (tid & 31) * 4;

    float acc[4][4][4];
    #pragma unroll
    for (int mf = 0; mf < 4; mf++)
        #pragma unroll
        for (int nf = 0; nf < 4; nf++)
            #pragma unroll
            for (int e = 0; e < 4; e++) acc[mf][nf][e] = 0.f;

    auto loadChunk = [&](int k0, int buf) {
        unsigned* Ad = smu + buf * (GA + GB);
        unsigned* Bd = Ad + GA;
        #pragma unroll
        for (int it = 0; it < 4; it++) {
            const int r = ar + it * 32;
            CP16(sptr(&Ad[r * 36 + ac]),
                 &A[(size_t)(row0 + r) * K + k0 + ac]);
        }
        #pragma unroll
        for (int it = 0; it < 4; it++) {
            const int r = br + it * 8;
            CP16(sptr(&Bd[r * 136 + bc]),
                 &W[(size_t)(k0 + r) * NN + col0 + bc]);
        }
        CP_COMMIT();
    };

    const int nch = K >> 5;
    loadChunk(0, 0);
    loadChunk(32, 1);

    int buf = 0;
    for (int ch = 0; ch < nch; ch++) {
        if (ch + 1 < nch) { CP_WAIT(1); } else { CP_WAIT(0); }
        __syncthreads();
        if (ch + 2 < nch)
            loadChunk((ch + 2) * 32, (buf + 2) % GSTAGES);

        const unsigned* Ab = smu + buf * (GA + GB);
        const unsigned* Bb = Ab + GA;
        #pragma unroll
        for (int ks = 0; ks < 4; ks++) {
            unsigned a[4][4], b[4][2];
            #pragma unroll
            for (int mf = 0; mf < 4; mf++) {
                const unsigned* p = &Ab[(wm * 64 + mf * 16 + lr) * 36 + ks * 8 + lc];
                a[mf][0] = p[0]; a[mf][1] = p[288]; a[mf][2] = p[4]; a[mf][3] = p[292];
            }
            #pragma unroll
            for (int nf = 0; nf < 4; nf++) {
                const unsigned* p = &Bb[(ks * 8 + lc) * 136 + wn * 32 + nf * 8 + lr];
                b[nf][0] = p[0]; b[nf][1] = p[544];
            }
            #pragma unroll
            for (int mf = 0; mf < 4; mf++)
                #pragma unroll
                for (int nf = 0; nf < 4; nf++)
                    mma8(acc[mf][nf], a[mf], b[nf]);
        }
        buf = (buf + 1) % GSTAGES;
        __syncthreads();
    }

    // Epilogue
    #pragma unroll
    for (int mf = 0; mf < 4; mf++) {
        #pragma unroll
        for (int hf = 0; hf < 2; hf++) {
            const int m  = row0 + wm * 64 + mf * 16 + lr + hf * 8;
            const int bb = m >> 11;
            const int ii = m & 2047;
            #pragma unroll
            for (int nf = 0; nf < 4; nf++) {
                const int col = col0 + wn * 32 + nf * 8 + 2 * lc;
                float2 v = make_float2(acc[mf][nf][hf * 2], acc[mf][nf][hf * 2 + 1]);
                if (MODE == 0) {
                    v.x = f2tff(v.x * SCALE_); v.y = f2tff(v.y * SCALE_);
                    const int hh = col >> 6, dd = col & 63;
                    *(float2*)&g_q[(((size_t)(bb * H_ + hh)) * N_ + ii) * DH_ + dd] = v;
                } else if (MODE == 1) {
                    v.x = f2tff(v.x); v.y = f2tff(v.y);
                    if (col < DI_) {
                        const int hh = col >> 6, dd = col & 63;
                        *(float2*)&g_k[(((size_t)(bb * H_ + hh)) * N_ + ii) * DH_ + dd] = v;
                    } else {
                        const int c = col - DI_;
                        const int hh = c >> 6, dd = c & 63;
                        *(float2*)&g_v[(((size_t)(bb * H_ + hh)) * N_ + ii) * DH_ + dd] = v;
                    }
                } else if (MODE == 2) {
                    const size_t idx = (size_t)m * DI_ + col;
                    float2 ao  = *(const float2*)&g_att[idx];
                    float2 bgv = *(const float2*)&bg[col];
                    v.x = f2tff(ao.x / (1.f + __expf(-(v.x + bgv.x))));
                    v.y = f2tff(ao.y / (1.f + __expf(-(v.y + bgv.y))));
                    *(float2*)&g_gated[idx] = v;
                } else {
                    *(float2*)&out[(size_t)m * D_ + col] = v;
                }
            }
        }
    }
}

// ---------------------------------------------------------------------------
// Flash attention, tf32 tensor cores. Q/K/V arrive tf32-exact (no CVTs).
// Block = 128 q-rows of one (b,h); 8 warps each own 16 q-rows x full 64 j-tile
// (softmax warp-local). K/V tiles via cp.async; bias+mask LDGs issued under
// the cp.async wait + QK mma.
// ---------------------------------------------------------------------------
#define AQ (128 * 68)
#define AK (64 * 68)
#define AV (64 * 72)
#define AP (128 * 68)
#define ATT_SMEM_BYTES ((AQ + AK + AV + AP) * 4)

__global__ void __launch_bounds__(256, 2) fattn_kernel(
    const float* __restrict__ bias, const int* __restrict__ mask)
{
    extern __shared__ unsigned sm[];
    unsigned* Qs = sm;            // [q][d]  stride 68
    unsigned* Ks = Qs + AQ;       // [j][d]  stride 68
    unsigned* Vs = Ks + AK;       // [j][d]  stride 72
    unsigned* Ps = Vs + AV;       // [q][j]  stride 68 (warp-private rows)

    const int tid  = threadIdx.x;
    const int wid  = tid >> 5;
    const int lane = tid & 31;
    const int lr   = lane >> 2;
    const int lc   = lane & 3;
    const int bh   = blockIdx.y;
    const int b    = bh >> 4;
    const int h    = bh & 15;
    const int i0   = blockIdx.x * 128;
    const int q0   = wid * 16;

    const unsigned* qbase = (const unsigned*)(g_q + ((size_t)bh * N_ + i0) * DH_);
    const float* kbase = g_k + (size_t)bh * N_ * DH_;
    const float* vbase = g_v + (size_t)bh * N_ * DH_;
    const float* bp0 = bias + ((size_t)bh * N_ + i0 + q0 + lr) * N_;
    const float* bp1 = bp0 + 8 * (size_t)N_;
    const int* mbase = mask + (size_t)b * N_;

    // Load Q tile once (already tf32-exact: raw copy)
    #pragma unroll
    for (int it = 0; it < 8; it++) {
        const int i = tid + it * 256;
        const int r = i >> 4, c4 = (i & 15) * 4;
        *(uint4*)&Qs[r * 68 + c4] = *(const uint4*)&qbase[r * DH_ + c4];
    }

    float S[8][4], O[8][4];
    float mi0 = -1e30f, mi1 = -1e30f, li0 = 0.f, li1 = 0.f;
    #pragma unroll
    for (int nf = 0; nf < 8; nf++)
        O[nf][0] = O[nf][1] = O[nf][2] = O[nf][3] = 0.f;

    const int lrow = tid >> 2;          // 0..63  (K/V row this thread loads)
    const int lcol = (tid & 3) * 4;     // 0,4,8,12 -> with *1: cols 0..15? use (tid&3)*4 of 16 floats
    // K/V tile row layout: 64 rows x 64 cols; 256 threads -> each thread 4x16B? Use: r=tid>>2 covers 64 rows, 4 threads x 16B = 64B per row; need 256B per row -> it loop 4 over col chunks.

    for (int t = 0; t < N_ / 64; t++) {
        const int j0 = t * 64;
        __syncthreads();   // all warps done with previous K/V/P tiles

        // Issue K/V tile loads (async)
        #pragma unroll
        for (int it = 0; it < 4; it++) {
            const int c4 = lcol + it * 16;
            CP16(sptr(&Ks[lrow * 68 + c4]), &kbase[(size_t)(j0 + lrow) * DH_ + c4]);
            CP16(sptr(&Vs[lrow * 72 + c4]), &vbase[(size_t)(j0 + lrow) * DH_ + c4]);
        }
        CP_COMMIT();

        // Bias + mask preload (LDGs fly under the cp.async wait + mma)
        float2 bA[8], bB[8];
        #pragma unroll
        for (int nf = 0; nf < 8; nf++) {
            const int jc = nf * 8 + 2 * lc;
            int2  mv = *(const int2*)&mbase[j0 + jc];
            float2 t0 = *(const float2*)&bp0[j0 + jc];
            float2 t1 = *(const float2*)&bp1[j0 + jc];
            const float mx = mv.x ? 0.f : -1e30f;
            const float my = mv.y ? 0.f : -1e30f;
            bA[nf].x = t0.x + mx; bA[nf].y = t0.y + my;
            bB[nf].x = t1.x + mx; bB[nf].y = t1.y + my;
        }

        CP_WAIT(0);
        __syncthreads();

        // S = Q @ K^T (zero-init)
        #pragma unroll
        for (int nf = 0; nf < 8; nf++)
            S[nf][0] = S[nf][1] = S[nf][2] = S[nf][3] = 0.f;
        #pragma unroll
        for (int ks = 0; ks < 8; ks++) {
            unsigned a[4];
            const unsigned* pa = &Qs[(q0 + lr) * 68 + ks * 8 + lc];
            a[0] = pa[0]; a[1] = pa[544]; a[2] = pa[4]; a[3] = pa[548];
            #pragma unroll
            for (int nf = 0; nf < 8; nf++) {
                unsigned bf[2];
                const unsigned* pb = &Ks[(nf * 8 + lr) * 68 + ks * 8 + lc];
                bf[0] = pb[0]; bf[1] = pb[4];
                mma8(S[nf], a, bf);
            }
        }

        // Add bias+mask
        #pragma unroll
        for (int nf = 0; nf < 8; nf++) {
            S[nf][0] += bA[nf].x; S[nf][1] += bA[nf].y;
            S[nf][2] += bB[nf].x; S[nf][3] += bB[nf].y;
        }

        // Warp-local row max
        float m0 = -1e30f, m1 = -1e30f;
        #pragma unroll
        for (int nf = 0; nf < 8; nf++) {
            m0 = fmaxf(m0, fmaxf(S[nf][0], S[nf][1]));
            m1 = fmaxf(m1, fmaxf(S[nf][2], S[nf][3]));
        }
        m0 = fmaxf(m0, __shfl_xor_sync(~0u, m0, 1));
        m0 = fmaxf(m0, __shfl_xor_sync(~0u, m0, 2));
        m1 = fmaxf(m1, __shfl_xor_sync(~0u, m1, 1));
        m1 = fmaxf(m1, __shfl_xor_sync(~0u, m1, 2));

        const float mn0 = fmaxf(mi0, m0), mn1 = fmaxf(mi1, m1);
        const float cr0 = __expf(mi0 - mn0), cr1 = __expf(mi1 - mn1);
        mi0 = mn0; mi1 = mn1;

        float s0 = 0.f, s1 = 0.f;
        #pragma unroll
        for (int nf = 0; nf < 8; nf++) {
            S[nf][0] = __expf(S[nf][0] - mn0);
            S[nf][1] = __expf(S[nf][1] - mn0);
            S[nf][2] = __expf(S[nf][2] - mn1);
            S[nf][3] = __expf(S[nf][3] - mn1);
            s0 += S[nf][0] + S[nf][1];
            s1 += S[nf][2] + S[nf][3];
            O[nf][0] *= cr0; O[nf][1] *= cr0;
            O[nf][2] *= cr1; O[nf][3] *= cr1;
            uint2 u0 = make_uint2(f2tf(S[nf][0]), f2tf(S[nf][1]));
            *(uint2*)&Ps[(q0 + lr) * 68 + nf * 8 + 2 * lc] = u0;
            uint2 u1 = make_uint2(f2tf(S[nf][2]), f2tf(S[nf][3]));
            *(uint2*)&Ps[(q0 + lr + 8) * 68 + nf * 8 + 2 * lc] = u1;
        }
        s0 += __shfl_xor_sync(~0u, s0, 1);
        s0 += __shfl_xor_sync(~0u, s0, 2);
        s1 += __shfl_xor_sync(~0u, s1, 1);
        s1 += __shfl_xor_sync(~0u, s1, 2);
        li0 = li0 * cr0 + s0;
        li1 = li1 * cr1 + s1;

        __syncwarp();

        // O += P @ V  (P rows are warp-private)
        #pragma unroll
        for (int ks = 0; ks < 8; ks++) {
            unsigned a[4];
            const unsigned* pa = &Ps[(q0 + lr) * 68 + ks * 8 + lc];
            a[0] = pa[0]; a[1] = pa[544]; a[2] = pa[4]; a[3] = pa[548];
            #pragma unroll
            for (int nf = 0; nf < 8; nf++) {
                unsigned bf[2];
                const unsigned* pb = &Vs[(ks * 8 + lc) * 72 + nf * 8 + lr];
                bf[0] = pb[0]; bf[1] = pb[288];
                mma8(O[nf], a, bf);
            }
        }
    }

    // Normalize + write token-major [b, i, h*64 + d]
    const float inv0 = 1.f / li0, inv1 = 1.f / li1;
    const size_t r0 = ((size_t)b * N_ + i0 + q0 + lr) * DI_ + h * DH_;
    const size_t r1 = r0 + 8 * (size_t)DI_;
    #pragma unroll
    for (int nf = 0; nf < 8; nf++) {
        const int dd = nf * 8 + 2 * lc;
        *(float2*)&g_att[r0 + dd] = make_float2(O[nf][0] * inv0, O[nf][1] * inv0);
        *(float2*)&g_att[r1 + dd] = make_float2(O[nf][2] * inv1, O[nf][3] * inv1);
    }
}

// ---------------------------------------------------------------------------
extern "C" void kernel_launch(void* const* d_in, const int* in_sizes, int n_in,
                              void* d_out, int out_size)
{
    const float* seq  = (const float*)d_in[0];
    const int*   mask = (const int*)d_in[1];
    const float* bias = (const float*)d_in[2];
    const float* Wq   = (const float*)d_in[3];
    const float* Wkv  = (const float*)d_in[4];
    const float* Wo   = (const float*)d_in[5];
    const float* Wg   = (const float*)d_in[6];
    const float* bg   = (const float*)d_in[7];
    float* out = (float*)d_out;

    cudaFuncSetAttribute(tgemm_kernel<0>,
        cudaFuncAttributeMaxDynamicSharedMemorySize, GEMM_SMEM_BYTES);
    cudaFuncSetAttribute(tgemm_kernel<1>,
        cudaFuncAttributeMaxDynamicSharedMemorySize, GEMM_SMEM_BYTES);
    cudaFuncSetAttribute(tgemm_kernel<2>,
        cudaFuncAttributeMaxDynamicSharedMemorySize, GEMM_SMEM_BYTES);
    cudaFuncSetAttribute(tgemm_kernel<3>,
        cudaFuncAttributeMaxDynamicSharedMemorySize, GEMM_SMEM_BYTES);
    cudaFuncSetAttribute(fattn_kernel,
        cudaFuncAttributeMaxDynamicSharedMemorySize, ATT_SMEM_BYTES);

    // Device-global addresses (host-side) for prepass destinations
    float *p_seq, *p_wq, *p_wkv, *p_wg, *p_wo;
    cudaGetSymbolAddress((void**)&p_seq, g_seq);
    cudaGetSymbolAddress((void**)&p_wq,  g_wq);
    cudaGetSymbolAddress((void**)&p_wkv, g_wkv);
    cudaGetSymbolAddress((void**)&p_wg,  g_wg);
    cudaGetSymbolAddress((void**)&p_wo,  g_wo);

    // Prepass: tf32-round all GEMM inputs (one cvt per element, ever)
    round_tf32_kernel<<<2048, 256>>>((const float4*)seq, (float4*)p_seq,
                                     B_*N_*D_/4);
    round_tf32_kernel<<<1024, 256>>>((const float4*)Wq,  (float4*)p_wq,
                                     D_*DI_/4);
    round_tf32_kernel<<<2048, 256>>>((const float4*)Wkv, (float4*)p_wkv,
                                     D_*2*DI_/4);
    round_tf32_kernel<<<1024, 256>>>((const float4*)Wg,  (float4*)p_wg,
                                     D_*DI_/4);
    round_tf32_kernel<<<1024, 256>>>((const float4*)Wo,  (float4*)p_wo,
                                     DI_*D_/4);

    tgemm_kernel<0><<<dim3(DI_ / 128, (B_ * N_) / 128), 256, GEMM_SMEM_BYTES>>>(
        p_seq, p_wq, D_, DI_, nullptr, nullptr);
    tgemm_kernel<1><<<dim3((2 * DI_) / 128, (B_ * N_) / 128), 256, GEMM_SMEM_BYTES>>>(
        p_seq, p_wkv, D_, 2 * DI_, nullptr, nullptr);
    fattn_kernel<<<dim3(N_ / 128, B_ * H_), 256, ATT_SMEM_BYTES>>>(bias, mask);
    tgemm_kernel<2><<<dim3(DI_ / 128, (B_ * N_) / 128), 256, GEMM_SMEM_BYTES>>>(
        p_seq, p_wg, D_, DI_, bg, nullptr);
    // MODE 3 reads g_gated via symbol: pass its address as A for uniformity
    float* p_gated;
    cudaGetSymbolAddress((void**)&p_gated, g_gated);
    tgemm_kernel<3><<<dim3(D_ / 128, (B_ * N_) / 128), 256, GEMM_SMEM_BYTES>>>(
        p_gated, p_wo, DI_, D_, nullptr, out);
}

// round 9
// speedup vs baseline: 3.0985x; 1.0564x over previous
#include <cuda_runtime.h>

// Problem constants
#define B_  2
#define N_  2048
#define D_  1024
#define H_  16
#define DH_ 64
#define DI_ 1024
#define LOG2E_ 1.4426950408889634f
#define QSCALE_ (0.125f * LOG2E_)   // attention scale * log2e (base-2 softmax)

// Scratch (device globals: allocation-free per harness rules)
__device__ float g_q[B_*H_*N_*DH_];      // tf32-exact, *QSCALE folded
__device__ float g_k[B_*H_*N_*DH_];      // tf32-exact
__device__ float g_v[B_*H_*N_*DH_];      // tf32-exact
__device__ float g_att[B_*N_*DI_];       // full f32
__device__ float g_gated[B_*N_*DI_];     // tf32-exact
// tf32-rounded inputs (prepass)
__device__ float g_seq[B_*N_*D_];
__device__ float g_wqkv[D_*3*DI_];       // row k = Wq[k] (1024) ++ Wkv[k] (2048)
__device__ float g_wg [D_*DI_];
__device__ float g_wo [DI_*D_];

// ---------------------------------------------------------------------------
// helpers
// ---------------------------------------------------------------------------
__device__ __forceinline__ unsigned f2tf(float x) {
    unsigned r;
    asm("cvt.rna.tf32.f32 %0, %1;" : "=r"(r) : "f"(x));
    return r;
}
__device__ __forceinline__ float f2tff(float x) {
    return __uint_as_float(f2tf(x));
}
__device__ __forceinline__ float ex2f(float x) {
    float y;
    asm("ex2.approx.f32 %0, %1;" : "=f"(y) : "f"(x));
    return y;
}

__device__ __forceinline__ void mma8(float* c, const unsigned* a, const unsigned* b) {
    asm volatile(
        "mma.sync.aligned.m16n8k8.row.col.f32.tf32.tf32.f32 "
        "{%0,%1,%2,%3},{%4,%5,%6,%7},{%8,%9},{%0,%1,%2,%3};"
        : "+f"(c[0]), "+f"(c[1]), "+f"(c[2]), "+f"(c[3])
        : "r"(a[0]), "r"(a[1]), "r"(a[2]), "r"(a[3]), "r"(b[0]), "r"(b[1]));
}

__device__ __forceinline__ unsigned sptr(const void* p) {
    return (unsigned)__cvta_generic_to_shared(p);
}
#define CP16(dst, src) \
    asm volatile("cp.async.cg.shared.global [%0], [%1], 16;" :: "r"(dst), "l"(src))
#define CP_COMMIT() asm volatile("cp.async.commit_group;" ::: "memory")
#define CP_WAIT(n)  asm volatile("cp.async.wait_group %0;" :: "n"(n) : "memory")

// ---------------------------------------------------------------------------
// Prepass (single launch): tf32-round seq / Wq / Wkv / Wg / Wo.
// Wq and Wkv are interleaved into g_wqkv: row k = [Wq[k] | Wkv[k]] (3072 wide).
// Region sizes in float4: seq 1048576, wq 262144, wkv 524288, wg 262144, wo 262144.
// ---------------------------------------------------------------------------
#define PREP_TOTAL4 2359296
__global__ void prep_kernel(const float4* __restrict__ seq,
                            const float4* __restrict__ wq,
                            const float4* __restrict__ wkv,
                            const float4* __restrict__ wg,
                            const float4* __restrict__ wo)
{
    const int i = blockIdx.x * blockDim.x + threadIdx.x;
    if (i >= PREP_TOTAL4) return;
    float4 v;
    float4* dst;
    if (i < 1048576) {
        v = seq[i];
        dst = (float4*)g_seq + i;
    } else if (i < 1048576 + 262144) {
        const int j = i - 1048576;
        v = wq[j];
        dst = (float4*)g_wqkv + ((j >> 8) * 768 + (j & 255));
    } else if (i < 1048576 + 262144 + 524288) {
        const int j = i - (1048576 + 262144);
        v = wkv[j];
        dst = (float4*)g_wqkv + ((j >> 9) * 768 + 256 + (j & 511));
    } else if (i < 1048576 + 262144 + 524288 + 262144) {
        const int j = i - (1048576 + 262144 + 524288);
        v = wg[j];
        dst = (float4*)g_wg + j;
    } else {
        const int j = i - (1048576 + 262144 + 524288 + 262144);
        v = wo[j];
        dst = (float4*)g_wo + j;
    }
    v.x = f2tff(v.x); v.y = f2tff(v.y); v.z = f2tff(v.z); v.w = f2tff(v.w);
    *dst = v;
}

// ---------------------------------------------------------------------------
// tf32 tensor-core GEMM, 3-stage cp.async pipeline, ONE sync per chunk.
// Inputs tf32-exact f32: raw bits feed mma (zero CVTs in inner loop).
// C[M,NN] = A[M,K] @ W[K,NN]; 128x128 block, K-chunk 32; 8 warps 2(M)x4(N).
// MODE 0: fused QKV proj (NN=3072) -> g_q (*QSCALE) / g_k / g_v (head split)
// MODE 2: gate -> g_gated = round_tf32(g_att * sigmoid(acc + bg))
// MODE 3: out -> out = g_gated @ Wo (plain f32 store)
// ---------------------------------------------------------------------------
#define GA 4608   // 128*36 words per A buffer (bank = 4*row + k)
#define GB 4352   // 32*136 words per B buffer (bank = 8*k + n)
#define GSTAGES 3
#define GEMM_SMEM_BYTES (GSTAGES * (GA + GB) * 4)

template<int MODE>
__global__ void __launch_bounds__(256, 2) tgemm_kernel(
    const float* __restrict__ A, const float* __restrict__ W,
    int K, int NN, const float* __restrict__ bg, float* __restrict__ out)
{
    extern __shared__ unsigned smu[];

    const int tid  = threadIdx.x;
    const int wid  = tid >> 5;
    const int lane = tid & 31;
    const int lr   = lane >> 2;
    const int lc   = lane & 3;
    const int wm   = wid >> 2;
    const int wn   = wid & 3;
    const int row0 = blockIdx.y * 128;
    const int col0 = blockIdx.x * 128;

    const int ar = tid >> 3, ac = (tid & 7) * 4;
    const int br = tid >> 5, bc = (tid & 31) * 4;

    float acc[4][4][4];
    #pragma unroll
    for (int mf = 0; mf < 4; mf++)
        #pragma unroll
        for (int nf = 0; nf < 4; nf++)
            #pragma unroll
            for (int e = 0; e < 4; e++) acc[mf][nf][e] = 0.f;

    auto loadChunk = [&](int k0, int buf) {
        unsigned* Ad = smu + buf * (GA + GB);
        unsigned* Bd = Ad + GA;
        #pragma unroll
        for (int it = 0; it < 4; it++) {
            const int r = ar + it * 32;
            CP16(sptr(&Ad[r * 36 + ac]),
                 &A[(size_t)(row0 + r) * K + k0 + ac]);
        }
        #pragma unroll
        for (int it = 0; it < 4; it++) {
            const int r = br + it * 8;
            CP16(sptr(&Bd[r * 136 + bc]),
                 &W[(size_t)(k0 + r) * NN + col0 + bc]);
        }
        CP_COMMIT();
    };

    const int nch = K >> 5;
    loadChunk(0, 0);
    loadChunk(32, 1);

    int buf = 0;
    for (int ch = 0; ch < nch; ch++) {
        if (ch + 1 < nch) { CP_WAIT(1); } else { CP_WAIT(0); }
        __syncthreads();   // chunk visible AND all warps past compute(ch-1)
        if (ch + 2 < nch)
            loadChunk((ch + 2) * 32, (buf + 2) % GSTAGES);

        const unsigned* Ab = smu + buf * (GA + GB);
        const unsigned* Bb = Ab + GA;
        #pragma unroll
        for (int ks = 0; ks < 4; ks++) {
            unsigned a[4][4], b[4][2];
            #pragma unroll
            for (int mf = 0; mf < 4; mf++) {
                const unsigned* p = &Ab[(wm * 64 + mf * 16 + lr) * 36 + ks * 8 + lc];
                a[mf][0] = p[0]; a[mf][1] = p[288]; a[mf][2] = p[4]; a[mf][3] = p[292];
            }
            #pragma unroll
            for (int nf = 0; nf < 4; nf++) {
                const unsigned* p = &Bb[(ks * 8 + lc) * 136 + wn * 32 + nf * 8 + lr];
                b[nf][0] = p[0]; b[nf][1] = p[544];
            }
            #pragma unroll
            for (int mf = 0; mf < 4; mf++)
                #pragma unroll
                for (int nf = 0; nf < 4; nf++)
                    mma8(acc[mf][nf], a[mf], b[nf]);
        }
        buf = (buf + 1) % GSTAGES;
    }

    // Epilogue
    #pragma unroll
    for (int mf = 0; mf < 4; mf++) {
        #pragma unroll
        for (int hf = 0; hf < 2; hf++) {
            const int m  = row0 + wm * 64 + mf * 16 + lr + hf * 8;
            const int bb = m >> 11;
            const int ii = m & 2047;
            #pragma unroll
            for (int nf = 0; nf < 4; nf++) {
                const int col = col0 + wn * 32 + nf * 8 + 2 * lc;
                float2 v = make_float2(acc[mf][nf][hf * 2], acc[mf][nf][hf * 2 + 1]);
                if (MODE == 0) {
                    if (col < DI_) {            // Q (log2e*scale folded)
                        v.x = f2tff(v.x * QSCALE_); v.y = f2tff(v.y * QSCALE_);
                        const int hh = col >> 6, dd = col & 63;
                        *(float2*)&g_q[(((size_t)(bb * H_ + hh)) * N_ + ii) * DH_ + dd] = v;
                    } else if (col < 2 * DI_) { // K
                        v.x = f2tff(v.x); v.y = f2tff(v.y);
                        const int c = col - DI_;
                        const int hh = c >> 6, dd = c & 63;
                        *(float2*)&g_k[(((size_t)(bb * H_ + hh)) * N_ + ii) * DH_ + dd] = v;
                    } else {                    // V
                        v.x = f2tff(v.x); v.y = f2tff(v.y);
                        const int c = col - 2 * DI_;
                        const int hh = c >> 6, dd = c & 63;
                        *(float2*)&g_v[(((size_t)(bb * H_ + hh)) * N_ + ii) * DH_ + dd] = v;
                    }
                } else if (MODE == 2) {
                    const size_t idx = (size_t)m * DI_ + col;
                    float2 ao  = *(const float2*)&g_att[idx];
                    float2 bgv = *(const float2*)&bg[col];
                    v.x = f2tff(ao.x / (1.f + __expf(-(v.x + bgv.x))));
                    v.y = f2tff(ao.y / (1.f + __expf(-(v.y + bgv.y))));
                    *(float2*)&g_gated[idx] = v;
                } else {
                    *(float2*)&out[(size_t)m * D_ + col] = v;
                }
            }
        }
    }
}

// ---------------------------------------------------------------------------
// Flash attention, tf32 tensor cores, base-2 softmax (log2e folded into Q).
// Block = 128 q-rows of one (b,h); 8 warps each own 16 q-rows x full 64 j-tile.
// Pipeline: V(t) cp.async at tile start (hides under QK mma); K(t+1) issued
// right after QK consumed Ks (hides under softmax + PV + next-tile entry).
// ---------------------------------------------------------------------------
#define AQ (128 * 68)
#define AK (64 * 68)
#define AV (64 * 72)
#define AP (128 * 68)
#define ATT_SMEM_BYTES ((AQ + AK + AV + AP) * 4)

__global__ void __launch_bounds__(256, 2) fattn_kernel(
    const float* __restrict__ bias, const int* __restrict__ mask)
{
    extern __shared__ unsigned sm[];
    unsigned* Qs = sm;            // [q][d]  stride 68
    unsigned* Ks = Qs + AQ;       // [j][d]  stride 68
    unsigned* Vs = Ks + AK;       // [j][d]  stride 72
    unsigned* Ps = Vs + AV;       // [q][j]  stride 68 (warp-private rows)

    const int tid  = threadIdx.x;
    const int wid  = tid >> 5;
    const int lane = tid & 31;
    const int lr   = lane >> 2;
    const int lc   = lane & 3;
    const int bh   = blockIdx.y;
    const int b    = bh >> 4;
    const int h    = bh & 15;
    const int i0   = blockIdx.x * 128;
    const int q0   = wid * 16;

    const unsigned* qbase = (const unsigned*)(g_q + ((size_t)bh * N_ + i0) * DH_);
    const float* kbase = g_k + (size_t)bh * N_ * DH_;
    const float* vbase = g_v + (size_t)bh * N_ * DH_;
    const float* bp0 = bias + ((size_t)bh * N_ + i0 + q0 + lr) * N_;
    const float* bp1 = bp0 + 8 * (size_t)N_;
    const int* mbase = mask + (size_t)b * N_;

    const int lrow = tid >> 2;          // 0..63 (K/V row this thread loads)
    const int lcol = (tid & 3) * 4;     // col chunk base

    // Prologue: K(0) async; Q tile raw copy (tf32-exact already)
    #pragma unroll
    for (int it = 0; it < 4; it++) {
        const int c4 = lcol + it * 16;
        CP16(sptr(&Ks[lrow * 68 + c4]), &kbase[(size_t)lrow * DH_ + c4]);
    }
    CP_COMMIT();

    #pragma unroll
    for (int it = 0; it < 8; it++) {
        const int i = tid + it * 256;
        const int r = i >> 4, c4 = (i & 15) * 4;
        *(uint4*)&Qs[r * 68 + c4] = *(const uint4*)&qbase[r * DH_ + c4];
    }

    float S[8][4], O[8][4];
    float mi0 = -1e30f, mi1 = -1e30f, li0 = 0.f, li1 = 0.f;
    #pragma unroll
    for (int nf = 0; nf < 8; nf++)
        O[nf][0] = O[nf][1] = O[nf][2] = O[nf][3] = 0.f;

    const int NT = N_ / 64;
    for (int t = 0; t < NT; t++) {
        const int j0 = t * 64;
        CP_WAIT(0);
        __syncthreads();   // K(t) visible; prior tile fully done with Vs/Ps

        // Issue V(t) (hides under bias LDG + QK mma + softmax)
        #pragma unroll
        for (int it = 0; it < 4; it++) {
            const int c4 = lcol + it * 16;
            CP16(sptr(&Vs[lrow * 72 + c4]), &vbase[(size_t)(j0 + lrow) * DH_ + c4]);
        }
        CP_COMMIT();

        // Bias*log2e + mask preload (LDGs fly under the QK mma)
        float2 bA[8], bB[8];
        #pragma unroll
        for (int nf = 0; nf < 8; nf++) {
            const int jc = nf * 8 + 2 * lc;
            int2  mv = *(const int2*)&mbase[j0 + jc];
            float2 t0 = *(const float2*)&bp0[j0 + jc];
            float2 t1 = *(const float2*)&bp1[j0 + jc];
            const float mx = mv.x ? 0.f : -1e30f;
            const float my = mv.y ? 0.f : -1e30f;
            bA[nf].x = fmaf(t0.x, LOG2E_, mx); bA[nf].y = fmaf(t0.y, LOG2E_, my);
            bB[nf].x = fmaf(t1.x, LOG2E_, mx); bB[nf].y = fmaf(t1.y, LOG2E_, my);
        }

        // S = Q @ K^T (log2-domain; Q carries scale*log2e)
        #pragma unroll
        for (int nf = 0; nf < 8; nf++)
            S[nf][0] = S[nf][1] = S[nf][2] = S[nf][3] = 0.f;
        #pragma unroll
        for (int ks = 0; ks < 8; ks++) {
            unsigned a[4];
            const unsigned* pa = &Qs[(q0 + lr) * 68 + ks * 8 + lc];
            a[0] = pa[0]; a[1] = pa[544]; a[2] = pa[4]; a[3] = pa[548];
            #pragma unroll
            for (int nf = 0; nf < 8; nf++) {
                unsigned bf[2];
                const unsigned* pb = &Ks[(nf * 8 + lr) * 68 + ks * 8 + lc];
                bf[0] = pb[0]; bf[1] = pb[4];
                mma8(S[nf], a, bf);
            }
        }

        __syncthreads();   // all warps done reading Ks
        // Prefetch K(t+1) into Ks (hides under softmax + PV + next-tile entry)
        if (t + 1 < NT) {
            #pragma unroll
            for (int it = 0; it < 4; it++) {
                const int c4 = lcol + it * 16;
                CP16(sptr(&Ks[lrow * 68 + c4]),
                     &kbase[(size_t)(j0 + 64 + lrow) * DH_ + c4]);
            }
        }
        CP_COMMIT();       // commit even when empty: keeps group counts aligned

        // Add bias+mask (log2 domain)
        #pragma unroll
        for (int nf = 0; nf < 8; nf++) {
            S[nf][0] += bA[nf].x; S[nf][1] += bA[nf].y;
            S[nf][2] += bB[nf].x; S[nf][3] += bB[nf].y;
        }

        // Warp-local row max
        float m0 = -1e30f, m1 = -1e30f;
        #pragma unroll
        for (int nf = 0; nf < 8; nf++) {
            m0 = fmaxf(m0, fmaxf(S[nf][0], S[nf][1]));
            m1 = fmaxf(m1, fmaxf(S[nf][2], S[nf][3]));
        }
        m0 = fmaxf(m0, __shfl_xor_sync(~0u, m0, 1));
        m0 = fmaxf(m0, __shfl_xor_sync(~0u, m0, 2));
        m1 = fmaxf(m1, __shfl_xor_sync(~0u, m1, 1));
        m1 = fmaxf(m1, __shfl_xor_sync(~0u, m1, 2));

        const float mn0 = fmaxf(mi0, m0), mn1 = fmaxf(mi1, m1);
        const float cr0 = ex2f(mi0 - mn0), cr1 = ex2f(mi1 - mn1);
        mi0 = mn0; mi1 = mn1;

        float s0 = 0.f, s1 = 0.f;
        #pragma unroll
        for (int nf = 0; nf < 8; nf++) {
            S[nf][0] = ex2f(S[nf][0] - mn0);
            S[nf][1] = ex2f(S[nf][1] - mn0);
            S[nf][2] = ex2f(S[nf][2] - mn1);
            S[nf][3] = ex2f(S[nf][3] - mn1);
            s0 += S[nf][0] + S[nf][1];
            s1 += S[nf][2] + S[nf][3];
            O[nf][0] *= cr0; O[nf][1] *= cr0;
            O[nf][2] *= cr1; O[nf][3] *= cr1;
            uint2 u0 = make_uint2(f2tf(S[nf][0]), f2tf(S[nf][1]));
            *(uint2*)&Ps[(q0 + lr) * 68 + nf * 8 + 2 * lc] = u0;
            uint2 u1 = make_uint2(f2tf(S[nf][2]), f2tf(S[nf][3]));
            *(uint2*)&Ps[(q0 + lr + 8) * 68 + nf * 8 + 2 * lc] = u1;
        }
        s0 += __shfl_xor_sync(~0u, s0, 1);
        s0 += __shfl_xor_sync(~0u, s0, 2);
        s1 += __shfl_xor_sync(~0u, s1, 1);
        s1 += __shfl_xor_sync(~0u, s1, 2);
        li0 = li0 * cr0 + s0;
        li1 = li1 * cr1 + s1;

        __syncwarp();

        CP_WAIT(1);        // V(t) done (K(t+1) group may stay pending)
        __syncthreads();   // V visible across threads

        // O += P @ V  (P rows warp-private)
        #pragma unroll
        for (int ks = 0; ks < 8; ks++) {
            unsigned a[4];
            const unsigned* pa = &Ps[(q0 + lr) * 68 + ks * 8 + lc];
            a[0] = pa[0]; a[1] = pa[544]; a[2] = pa[4]; a[3] = pa[548];
            #pragma unroll
            for (int nf = 0; nf < 8; nf++) {
                unsigned bf[2];
                const unsigned* pb = &Vs[(ks * 8 + lc) * 72 + nf * 8 + lr];
                bf[0] = pb[0]; bf[1] = pb[288];
                mma8(O[nf], a, bf);
            }
        }
    }

    // Normalize + write token-major [b, i, h*64 + d]
    const float inv0 = 1.f / li0, inv1 = 1.f / li1;
    const size_t r0 = ((size_t)b * N_ + i0 + q0 + lr) * DI_ + h * DH_;
    const size_t r1 = r0 + 8 * (size_t)DI_;
    #pragma unroll
    for (int nf = 0; nf < 8; nf++) {
        const int dd = nf * 8 + 2 * lc;
        *(float2*)&g_att[r0 + dd] = make_float2(O[nf][0] * inv0, O[nf][1] * inv0);
        *(float2*)&g_att[r1 + dd] = make_float2(O[nf][2] * inv1, O[nf][3] * inv1);
    }
}

// ---------------------------------------------------------------------------
extern "C" void kernel_launch(void* const* d_in, const int* in_sizes, int n_in,
                              void* d_out, int out_size)
{
    const float* seq  = (const float*)d_in[0];
    const int*   mask = (const int*)d_in[1];
    const float* bias = (const float*)d_in[2];
    const float* Wq   = (const float*)d_in[3];
    const float* Wkv  = (const float*)d_in[4];
    const float* Wo   = (const float*)d_in[5];
    const float* Wg   = (const float*)d_in[6];
    const float* bg   = (const float*)d_in[7];
    float* out = (float*)d_out;

    cudaFuncSetAttribute(tgemm_kernel<0>,
        cudaFuncAttributeMaxDynamicSharedMemorySize, GEMM_SMEM_BYTES);
    cudaFuncSetAttribute(tgemm_kernel<2>,
        cudaFuncAttributeMaxDynamicSharedMemorySize, GEMM_SMEM_BYTES);
    cudaFuncSetAttribute(tgemm_kernel<3>,
        cudaFuncAttributeMaxDynamicSharedMemorySize, GEMM_SMEM_BYTES);
    cudaFuncSetAttribute(fattn_kernel,
        cudaFuncAttributeMaxDynamicSharedMemorySize, ATT_SMEM_BYTES);

    float *p_seq, *p_wqkv, *p_wg, *p_wo, *p_gated;
    cudaGetSymbolAddress((void**)&p_seq,   g_seq);
    cudaGetSymbolAddress((void**)&p_wqkv,  g_wqkv);
    cudaGetSymbolAddress((void**)&p_wg,    g_wg);
    cudaGetSymbolAddress((void**)&p_wo,    g_wo);
    cudaGetSymbolAddress((void**)&p_gated, g_gated);

    // Prepass: one launch, all tensors
    prep_kernel<<<(PREP_TOTAL4 + 255) / 256, 256>>>(
        (const float4*)seq, (const float4*)Wq, (const float4*)Wkv,
        (const float4*)Wg, (const float4*)Wo);

    // Fused QKV projection: [4096,1024] @ [1024,3072]
    tgemm_kernel<0><<<dim3(3 * DI_ / 128, (B_ * N_) / 128), 256, GEMM_SMEM_BYTES>>>(
        p_seq, p_wqkv, D_, 3 * DI_, nullptr, nullptr);
    // Attention
    fattn_kernel<<<dim3(N_ / 128, B_ * H_), 256, ATT_SMEM_BYTES>>>(bias, mask);
    // Gate GEMM + fused sigmoid * attn_out
    tgemm_kernel<2><<<dim3(DI_ / 128, (B_ * N_) / 128), 256, GEMM_SMEM_BYTES>>>(
        p_seq, p_wg, D_, DI_, bg, nullptr);
    // Output projection
    tgemm_kernel<3><<<dim3(D_ / 128, (B_ * N_) / 128), 256, GEMM_SMEM_BYTES>>>(
        p_gated, p_wo, DI_, D_, nullptr, out);
}

// round 11
// speedup vs baseline: 3.3063x; 1.0671x over previous
#include <cuda_runtime.h>

// Problem constants
#define B_  2
#define N_  2048
#define D_  1024
#define H_  16
#define DH_ 64
#define DI_ 1024
#define LOG2E_ 1.4426950408889634f
#define QSCALE_ (0.125f * LOG2E_)   // attention scale * log2e (base-2 softmax)

// Scratch (device globals: allocation-free per harness rules)
__device__ float g_q[B_*H_*N_*DH_];      // [b,h,n,d] tf32-exact, *QSCALE folded
__device__ float g_k[B_*H_*N_*DH_];      // [b,h,n,d] tf32-exact
__device__ float g_v[B_*H_*DH_*N_];      // [b,h,d,n] TRANSPOSED, tf32-exact
__device__ float g_att[B_*N_*DI_];       // full f32
__device__ float g_gated[B_*N_*DI_];     // tf32-exact
// tf32-rounded inputs (prepass); weights stored TRANSPOSED [out][in]
__device__ float g_seq[B_*N_*D_];
__device__ float g_wqkv[3*DI_*D_];       // row n: n<1024 Wq^T, else Wkv^T
__device__ float g_wg [DI_*D_];
__device__ float g_wo [D_*DI_];

// ---------------------------------------------------------------------------
// helpers
// ---------------------------------------------------------------------------
__device__ __forceinline__ unsigned f2tf(float x) {
    unsigned r;
    asm("cvt.rna.tf32.f32 %0, %1;" : "=r"(r) : "f"(x));
    return r;
}
__device__ __forceinline__ float f2tff(float x) {
    return __uint_as_float(f2tf(x));
}
__device__ __forceinline__ float ex2f(float x) {
    float y;
    asm("ex2.approx.f32 %0, %1;" : "=f"(y) : "f"(x));
    return y;
}

__device__ __forceinline__ void mma8(float* c, const unsigned* a, const unsigned* b) {
    asm volatile(
        "mma.sync.aligned.m16n8k8.row.col.f32.tf32.tf32.f32 "
        "{%0,%1,%2,%3},{%4,%5,%6,%7},{%8,%9},{%0,%1,%2,%3};"
        : "+f"(c[0]), "+f"(c[1]), "+f"(c[2]), "+f"(c[3])
        : "r"(a[0]), "r"(a[1]), "r"(a[2]), "r"(a[3]), "r"(b[0]), "r"(b[1]));
}

__device__ __forceinline__ unsigned sptr(const void* p) {
    return (unsigned)__cvta_generic_to_shared(p);
}
#define CP16(dst, src) \
    asm volatile("cp.async.cg.shared.global [%0], [%1], 16;" :: "r"(dst), "l"(src))
#define CP_COMMIT() asm volatile("cp.async.commit_group;" ::: "memory")
#define CP_WAIT(n)  asm volatile("cp.async.wait_group %0;" :: "n"(n) : "memory")
// ldmatrix x4 on 32-bit data: 4 8x16B tiles, addresses lane-dependent
#define LDSM4(r0, r1, r2, r3, addr) \
    asm volatile("ldmatrix.sync.aligned.m8n8.x4.shared.b16 {%0,%1,%2,%3}, [%4];" \
        : "=r"(r0), "=r"(r1), "=r"(r2), "=r"(r3) : "r"(addr))

// Lane-offset helpers for LDSM tile addressing (words):
// A-type frag (a0..a3): row += ((lane>>3)&1)*8 + (lane&7), k += ((lane>>4)&1)*4
// B-type frag (b0,b1 x2 n-tiles): row += ((lane>>4)&1)*8 + (lane&7), k += ((lane>>3)&1)*4

// ---------------------------------------------------------------------------
// Prepass A: round seq to tf32-exact (float4 elementwise)
// ---------------------------------------------------------------------------
__global__ void prep_seq_kernel(const float4* __restrict__ seq)
{
    const int i = blockIdx.x * blockDim.x + threadIdx.x;
    if (i >= B_*N_*D_/4) return;
    float4 v = seq[i];
    v.x = f2tff(v.x); v.y = f2tff(v.y); v.z = f2tff(v.z); v.w = f2tff(v.w);
    ((float4*)g_seq)[i] = v;
}

// ---------------------------------------------------------------------------
// Prepass B: transpose + round weights. In [1024][W] -> out [W][1024].
// 32x32 tiles via smem; tiles: Wq 1024, Wkv 2048, Wg 1024, Wo 1024 = 5120.
// ---------------------------------------------------------------------------
__global__ void prep_wT_kernel(const float* __restrict__ wq,
                               const float* __restrict__ wkv,
                               const float* __restrict__ wg,
                               const float* __restrict__ wo)
{
    __shared__ float t[32][33];
    int tt = blockIdx.x;
    const float* src;
    float* dst;
    int W, kt, nt, noff;
    if (tt < 1024)      { src = wq;  dst = g_wqkv; W = 1024; nt = tt & 31; kt = tt >> 5; noff = 0; }
    else if (tt < 3072) { tt -= 1024; src = wkv; dst = g_wqkv; W = 2048; nt = tt & 63; kt = tt >> 6; noff = 1024; }
    else if (tt < 4096) { tt -= 3072; src = wg;  dst = g_wg;  W = 1024; nt = tt & 31; kt = tt >> 5; noff = 0; }
    else                { tt -= 4096; src = wo;  dst = g_wo;  W = 1024; nt = tt & 31; kt = tt >> 5; noff = 0; }
    const int tx = threadIdx.x & 31, ty = threadIdx.x >> 5;
    #pragma unroll
    for (int i = 0; i < 4; i++)
        t[ty + 8*i][tx] = f2tff(src[(size_t)(kt*32 + ty + 8*i) * W + nt*32 + tx]);
    __syncthreads();
    #pragma unroll
    for (int i = 0; i < 4; i++)
        dst[(size_t)(noff + nt*32 + ty + 8*i) * 1024 + kt*32 + tx] = t[tx][ty + 8*i];
}

// ---------------------------------------------------------------------------
// tf32 GEMM, 3-stage cp.async, ldmatrix fragment loads.
// C[M,NN] = A[M,K] @ W^T  where Wt is [NN][K] (weights pre-transposed).
// 128x128 block, K-chunk 32; 8 warps 2(M)x4(N).
// MODE 0: fused QKV -> g_q(*QSCALE)/g_k (head split) + g_v TRANSPOSED
// MODE 2: gate -> g_gated = round_tf32(g_att * sigmoid(acc + bg))
// MODE 3: out -> out (plain f32)
// ---------------------------------------------------------------------------
#define GA 4608   // 128*36 words A buffer  (As[m][k], pad 4)
#define GB 4608   // 128*36 words B buffer  (Bs[n][k], pad 4)
#define GSTAGES 3
#define GEMM_SMEM_BYTES (GSTAGES * (GA + GB) * 4)

template<int MODE>
__global__ void __launch_bounds__(256, 2) tgemm_kernel(
    const float* __restrict__ A, const float* __restrict__ Wt,
    int K, int NN, const float* __restrict__ bg, float* __restrict__ out)
{
    extern __shared__ unsigned smu[];

    const int tid  = threadIdx.x;
    const int wid  = tid >> 5;
    const int lane = tid & 31;
    const int lr   = lane >> 2;
    const int lc   = lane & 3;
    const int wm   = wid >> 2;
    const int wn   = wid & 3;
    const int row0 = blockIdx.y * 128;
    const int col0 = blockIdx.x * 128;

    const int ar = tid >> 3, ac = (tid & 7) * 4;   // 32 rows/iter x 8 float4

    // LDSM lane offsets (words)
    const int arow_l = ((lane >> 3) & 1) * 8 + (lane & 7);
    const int akof_l = ((lane >> 4) & 1) * 4;
    const int brow_l = ((lane >> 4) & 1) * 8 + (lane & 7);
    const int bkof_l = ((lane >> 3) & 1) * 4;
    const unsigned sbase = sptr(smu);
    const unsigned aOff = ((wm * 64 + arow_l) * 36 + akof_l) * 4;
    const unsigned bOff = (GA + (wn * 32 + brow_l) * 36 + bkof_l) * 4;

    float acc[4][4][4];
    #pragma unroll
    for (int mf = 0; mf < 4; mf++)
        #pragma unroll
        for (int nf = 0; nf < 4; nf++)
            #pragma unroll
            for (int e = 0; e < 4; e++) acc[mf][nf][e] = 0.f;

    auto loadChunk = [&](int k0, int buf) {
        unsigned* Ad = smu + buf * (GA + GB);
        unsigned* Bd = Ad + GA;
        #pragma unroll
        for (int it = 0; it < 4; it++) {
            const int r = ar + it * 32;
            CP16(sptr(&Ad[r * 36 + ac]),
                 &A[(size_t)(row0 + r) * K + k0 + ac]);
        }
        #pragma unroll
        for (int it = 0; it < 4; it++) {
            const int r = ar + it * 32;
            CP16(sptr(&Bd[r * 36 + ac]),
                 &Wt[(size_t)(col0 + r) * K + k0 + ac]);
        }
        CP_COMMIT();
    };

    const int nch = K >> 5;
    loadChunk(0, 0);
    loadChunk(32, 1);

    int buf = 0;
    for (int ch = 0; ch < nch; ch++) {
        if (ch + 1 < nch) { CP_WAIT(1); } else { CP_WAIT(0); }
        __syncthreads();
        if (ch + 2 < nch)
            loadChunk((ch + 2) * 32, (buf + 2) % GSTAGES);

        const unsigned cbase = sbase + buf * ((GA + GB) * 4);
        #pragma unroll
        for (int ks = 0; ks < 4; ks++) {
            unsigned a[4][4], b[4][2];
            #pragma unroll
            for (int mf = 0; mf < 4; mf++)
                LDSM4(a[mf][0], a[mf][1], a[mf][2], a[mf][3],
                      cbase + aOff + mf * (16*36*4) + ks * 32);
            #pragma unroll
            for (int p = 0; p < 2; p++)
                LDSM4(b[2*p][0], b[2*p][1], b[2*p+1][0], b[2*p+1][1],
                      cbase + bOff + p * (16*36*4) + ks * 32);
            #pragma unroll
            for (int mf = 0; mf < 4; mf++)
                #pragma unroll
                for (int nf = 0; nf < 4; nf++)
                    mma8(acc[mf][nf], a[mf], b[nf]);
        }
        buf = (buf + 1) % GSTAGES;
    }

    // Epilogue
    #pragma unroll
    for (int mf = 0; mf < 4; mf++) {
        #pragma unroll
        for (int hf = 0; hf < 2; hf++) {
            const int m  = row0 + wm * 64 + mf * 16 + lr + hf * 8;
            const int bb = m >> 11;
            const int ii = m & 2047;
            #pragma unroll
            for (int nf = 0; nf < 4; nf++) {
                const int col = col0 + wn * 32 + nf * 8 + 2 * lc;
                float2 v = make_float2(acc[mf][nf][hf * 2], acc[mf][nf][hf * 2 + 1]);
                if (MODE == 0) {
                    if (col < DI_) {            // Q (scale*log2e folded)
                        v.x = f2tff(v.x * QSCALE_); v.y = f2tff(v.y * QSCALE_);
                        const int hh = col >> 6, dd = col & 63;
                        *(float2*)&g_q[(((size_t)(bb * H_ + hh)) * N_ + ii) * DH_ + dd] = v;
                    } else if (col < 2 * DI_) { // K
                        v.x = f2tff(v.x); v.y = f2tff(v.y);
                        const int c = col - DI_;
                        const int hh = c >> 6, dd = c & 63;
                        *(float2*)&g_k[(((size_t)(bb * H_ + hh)) * N_ + ii) * DH_ + dd] = v;
                    } else {                    // V -> transposed [b,h,d,n]
                        const int c = col - 2 * DI_;
                        const int hh = c >> 6, dd = c & 63;
                        float* vb = &g_v[(((size_t)(bb * H_ + hh)) * DH_ + dd) * N_ + ii];
                        vb[0]  = f2tff(v.x);
                        vb[N_] = f2tff(v.y);
                    }
                } else if (MODE == 2) {
                    const size_t idx = (size_t)m * DI_ + col;
                    float2 ao  = *(const float2*)&g_att[idx];
                    float2 bgv = *(const float2*)&bg[col];
                    v.x = f2tff(ao.x / (1.f + __expf(-(v.x + bgv.x))));
                    v.y = f2tff(ao.y / (1.f + __expf(-(v.y + bgv.y))));
                    *(float2*)&g_gated[idx] = v;
                } else {
                    *(float2*)&out[(size_t)m * D_ + col] = v;
                }
            }
        }
    }
}

// ---------------------------------------------------------------------------
// Flash attention, tf32 + ldmatrix, base-2 softmax.
// Block = 128 q-rows of one (b,h); 8 warps each own 16 q-rows x full 64 j-tile.
// V is pre-transposed [d][n] so the PV B-operand is LDSM-loadable.
// Pipeline: V(t) cp.async at tile start; K(t+1) right after QK consumed Ks.
// ---------------------------------------------------------------------------
#define AQ (128 * 68)
#define AK (64 * 68)
#define AV (64 * 68)
#define AP (128 * 68)
#define ATT_SMEM_BYTES ((AQ + AK + AV + AP) * 4)

__global__ void __launch_bounds__(256, 2) fattn_kernel(
    const float* __restrict__ bias, const int* __restrict__ mask)
{
    extern __shared__ unsigned sm[];
    unsigned* Qs = sm;            // [q][d]  stride 68
    unsigned* Ks = Qs + AQ;       // [j][d]  stride 68
    unsigned* Vs = Ks + AK;       // [d][j]  stride 68 (transposed V)
    unsigned* Ps = Vs + AV;       // [q][j]  stride 68 (warp-private rows)

    const int tid  = threadIdx.x;
    const int wid  = tid >> 5;
    const int lane = tid & 31;
    const int lr   = lane >> 2;
    const int lc   = lane & 3;
    const int bh   = blockIdx.y;
    const int b    = bh >> 4;
    const int h    = bh & 15;
    const int i0   = blockIdx.x * 128;
    const int q0   = wid * 16;

    const unsigned* qbase = (const unsigned*)(g_q + ((size_t)bh * N_ + i0) * DH_);
    const float* kbase = g_k + (size_t)bh * N_ * DH_;
    const float* vbase = g_v + (size_t)bh * DH_ * N_;   // [d][n]
    const float* bp0 = bias + ((size_t)bh * N_ + i0 + q0 + lr) * N_;
    const float* bp1 = bp0 + 8 * (size_t)N_;
    const int* mbase = mask + (size_t)b * N_;

    const int lrow = tid >> 2;          // 0..63 (K j-row / V d-row to load)
    const int lcol = (tid & 3) * 4;

    // LDSM lane-dependent base addresses
    const int arow_l = ((lane >> 3) & 1) * 8 + (lane & 7);
    const int akof_l = ((lane >> 4) & 1) * 4;
    const int brow_l = ((lane >> 4) & 1) * 8 + (lane & 7);
    const int bkof_l = ((lane >> 3) & 1) * 4;
    const unsigned qAddr = sptr(Qs) + ((q0 + arow_l) * 68 + akof_l) * 4;
    const unsigned kAddr = sptr(Ks) + (brow_l * 68 + bkof_l) * 4;
    const unsigned vAddr = sptr(Vs) + (brow_l * 68 + bkof_l) * 4;
    const unsigned pAddr = sptr(Ps) + ((q0 + arow_l) * 68 + akof_l) * 4;

    // Prologue: K(0) async; Q tile raw copy (tf32-exact already)
    #pragma unroll
    for (int it = 0; it < 4; it++) {
        const int c4 = lcol + it * 16;
        CP16(sptr(&Ks[lrow * 68 + c4]), &kbase[(size_t)lrow * DH_ + c4]);
    }
    CP_COMMIT();

    #pragma unroll
    for (int it = 0; it < 8; it++) {
        const int i = tid + it * 256;
        const int r = i >> 4, c4 = (i & 15) * 4;
        *(uint4*)&Qs[r * 68 + c4] = *(const uint4*)&qbase[r * DH_ + c4];
    }

    float S[8][4], O[8][4];
    float mi0 = -1e30f, mi1 = -1e30f, li0 = 0.f, li1 = 0.f;
    #pragma unroll
    for (int nf = 0; nf < 8; nf++)
        O[nf][0] = O[nf][1] = O[nf][2] = O[nf][3] = 0.f;

    const int NT = N_ / 64;
    for (int t = 0; t < NT; t++) {
        const int j0 = t * 64;
        CP_WAIT(0);
        __syncthreads();   // K(t) visible; prior tile fully done with Vs/Ps

        // Issue V(t) (transposed rows: d -> j0..j0+63)
        #pragma unroll
        for (int it = 0; it < 4; it++) {
            const int c4 = lcol + it * 16;
            CP16(sptr(&Vs[lrow * 68 + c4]), &vbase[(size_t)lrow * N_ + j0 + c4]);
        }
        CP_COMMIT();

        // Bias*log2e + mask preload (flies under the QK mma)
        float2 bA[8], bB[8];
        #pragma unroll
        for (int nf = 0; nf < 8; nf++) {
            const int jc = nf * 8 + 2 * lc;
            int2  mv = *(const int2*)&mbase[j0 + jc];
            float2 t0 = *(const float2*)&bp0[j0 + jc];
            float2 t1 = *(const float2*)&bp1[j0 + jc];
            const float mx = mv.x ? 0.f : -1e30f;
            const float my = mv.y ? 0.f : -1e30f;
            bA[nf].x = fmaf(t0.x, LOG2E_, mx); bA[nf].y = fmaf(t0.y, LOG2E_, my);
            bB[nf].x = fmaf(t1.x, LOG2E_, mx); bB[nf].y = fmaf(t1.y, LOG2E_, my);
        }

        // S = Q @ K^T
        #pragma unroll
        for (int nf = 0; nf < 8; nf++)
            S[nf][0] = S[nf][1] = S[nf][2] = S[nf][3] = 0.f;
        #pragma unroll
        for (int ks = 0; ks < 8; ks++) {
            unsigned a[4];
            LDSM4(a[0], a[1], a[2], a[3], qAddr + ks * 32);
            #pragma unroll
            for (int p = 0; p < 4; p++) {
                unsigned bf[4];
                LDSM4(bf[0], bf[1], bf[2], bf[3],
                      kAddr + p * (16*68*4) + ks * 32);
                mma8(S[2*p],     a, &bf[0]);
                mma8(S[2*p + 1], a, &bf[2]);
            }
        }

        __syncthreads();   // all warps done reading Ks
        if (t + 1 < NT) {
            #pragma unroll
            for (int it = 0; it < 4; it++) {
                const int c4 = lcol + it * 16;
                CP16(sptr(&Ks[lrow * 68 + c4]),
                     &kbase[(size_t)(j0 + 64 + lrow) * DH_ + c4]);
            }
        }
        CP_COMMIT();

        // Add bias+mask (log2 domain)
        #pragma unroll
        for (int nf = 0; nf < 8; nf++) {
            S[nf][0] += bA[nf].x; S[nf][1] += bA[nf].y;
            S[nf][2] += bB[nf].x; S[nf][3] += bB[nf].y;
        }

        // Warp-local row max
        float m0 = -1e30f, m1 = -1e30f;
        #pragma unroll
        for (int nf = 0; nf < 8; nf++) {
            m0 = fmaxf(m0, fmaxf(S[nf][0], S[nf][1]));
            m1 = fmaxf(m1, fmaxf(S[nf][2], S[nf][3]));
        }
        m0 = fmaxf(m0, __shfl_xor_sync(~0u, m0, 1));
        m0 = fmaxf(m0, __shfl_xor_sync(~0u, m0, 2));
        m1 = fmaxf(m1, __shfl_xor_sync(~0u, m1, 1));
        m1 = fmaxf(m1, __shfl_xor_sync(~0u, m1, 2));

        const float mn0 = fmaxf(mi0, m0), mn1 = fmaxf(mi1, m1);
        const float cr0 = ex2f(mi0 - mn0), cr1 = ex2f(mi1 - mn1);
        mi0 = mn0; mi1 = mn1;

        float s0 = 0.f, s1 = 0.f;
        #pragma unroll
        for (int nf = 0; nf < 8; nf++) {
            S[nf][0] = ex2f(S[nf][0] - mn0);
            S[nf][1] = ex2f(S[nf][1] - mn0);
            S[nf][2] = ex2f(S[nf][2] - mn1);
            S[nf][3] = ex2f(S[nf][3] - mn1);
            s0 += S[nf][0] + S[nf][1];
            s1 += S[nf][2] + S[nf][3];
            O[nf][0] *= cr0; O[nf][1] *= cr0;
            O[nf][2] *= cr1; O[nf][3] *= cr1;
            uint2 u0 = make_uint2(f2tf(S[nf][0]), f2tf(S[nf][1]));
            *(uint2*)&Ps[(q0 + lr) * 68 + nf * 8 + 2 * lc] = u0;
            uint2 u1 = make_uint2(f2tf(S[nf][2]), f2tf(S[nf][3]));
            *(uint2*)&Ps[(q0 + lr + 8) * 68 + nf * 8 + 2 * lc] = u1;
        }
        s0 += __shfl_xor_sync(~0u, s0, 1);
        s0 += __shfl_xor_sync(~0u, s0, 2);
        s1 += __shfl_xor_sync(~0u, s1, 1);
        s1 += __shfl_xor_sync(~0u, s1, 2);
        li0 = li0 * cr0 + s0;
        li1 = li1 * cr1 + s1;

        __syncwarp();      // Ps rows are warp-private

        CP_WAIT(1);        // V(t) done (K(t+1) may stay pending)
        __syncthreads();   // V visible across threads

        // O += P @ V   (B-operand = V^T tiles in Vs[d][j])
        #pragma unroll
        for (int ks = 0; ks < 8; ks++) {
            unsigned a[4];
            LDSM4(a[0], a[1], a[2], a[3], pAddr + ks * 32);
            #pragma unroll
            for (int p = 0; p < 4; p++) {
                unsigned bf[4];
                LDSM4(bf[0], bf[1], bf[2], bf[3],
                      vAddr + p * (16*68*4) + ks * 32);
                mma8(O[2*p],     a, &bf[0]);
                mma8(O[2*p + 1], a, &bf[2]);
            }
        }
    }

    // Normalize + write token-major [b, i, h*64 + d]
    const float inv0 = 1.f / li0, inv1 = 1.f / li1;
    const size_t r0 = ((size_t)b * N_ + i0 + q0 + lr) * DI_ + h * DH_;
    const size_t r1 = r0 + 8 * (size_t)DI_;
    #pragma unroll
    for (int nf = 0; nf < 8; nf++) {
        const int dd = nf * 8 + 2 * lc;
        *(float2*)&g_att[r0 + dd] = make_float2(O[nf][0] * inv0, O[nf][1] * inv0);
        *(float2*)&g_att[r1 + dd] = make_float2(O[nf][2] * inv1, O[nf][3] * inv1);
    }
}

// ---------------------------------------------------------------------------
extern "C" void kernel_launch(void* const* d_in, const int* in_sizes, int n_in,
                              void* d_out, int out_size)
{
    const float* seq  = (const float*)d_in[0];
    const int*   mask = (const int*)d_in[1];
    const float* bias = (const float*)d_in[2];
    const float* Wq   = (const float*)d_in[3];
    const float* Wkv  = (const float*)d_in[4];
    const float* Wo   = (const float*)d_in[5];
    const float* Wg   = (const float*)d_in[6];
    const float* bg   = (const float*)d_in[7];
    float* out = (float*)d_out;

    cudaFuncSetAttribute(tgemm_kernel<0>,
        cudaFuncAttributeMaxDynamicSharedMemorySize, GEMM_SMEM_BYTES);
    cudaFuncSetAttribute(tgemm_kernel<2>,
        cudaFuncAttributeMaxDynamicSharedMemorySize, GEMM_SMEM_BYTES);
    cudaFuncSetAttribute(tgemm_kernel<3>,
        cudaFuncAttributeMaxDynamicSharedMemorySize, GEMM_SMEM_BYTES);
    cudaFuncSetAttribute(fattn_kernel,
        cudaFuncAttributeMaxDynamicSharedMemorySize, ATT_SMEM_BYTES);

    float *p_seq, *p_wqkv, *p_wg, *p_wo, *p_gated;
    cudaGetSymbolAddress((void**)&p_seq,   g_seq);
    cudaGetSymbolAddress((void**)&p_wqkv,  g_wqkv);
    cudaGetSymbolAddress((void**)&p_wg,    g_wg);
    cudaGetSymbolAddress((void**)&p_wo,    g_wo);
    cudaGetSymbolAddress((void**)&p_gated, g_gated);

    // Prepass: round seq; transpose+round all weights
    prep_seq_kernel<<<(B_*N_*D_/4 + 255) / 256, 256>>>((const float4*)seq);
    prep_wT_kernel<<<5120, 256>>>(Wq, Wkv, Wg, Wo);

    // Fused QKV projection: [4096,1024] @ Wqkv^T[3072,1024]
    tgemm_kernel<0><<<dim3(3 * DI_ / 128, (B_ * N_) / 128), 256, GEMM_SMEM_BYTES>>>(
        p_seq, p_wqkv, D_, 3 * DI_, nullptr, nullptr);
    // Attention
    fattn_kernel<<<dim3(N_ / 128, B_ * H_), 256, ATT_SMEM_BYTES>>>(bias, mask);
    // Gate GEMM + fused sigmoid * attn_out
    tgemm_kernel<2><<<dim3(DI_ / 128, (B_ * N_) / 128), 256, GEMM_SMEM_BYTES>>>(
        p_seq, p_wg, D_, DI_, bg, nullptr);
    // Output projection
    tgemm_kernel<3><<<dim3(D_ / 128, (B_ * N_) / 128), 256, GEMM_SMEM_BYTES>>>(
        p_gated, p_wo, DI_, D_, nullptr, out);
}

// round 13
// speedup vs baseline: 3.5460x; 1.0725x over previous
#include <cuda_runtime.h>

// Problem constants
#define B_  2
#define N_  2048
#define D_  1024
#define H_  16
#define DH_ 64
#define DI_ 1024
#define LOG2E_ 1.4426950408889634f
#define QSCALE_ (0.125f * LOG2E_)   // attention scale * log2e (base-2 softmax)

// Scratch (device globals: allocation-free per harness rules)
__device__ float g_q[B_*H_*N_*DH_];      // [b,h,n,d] tf32-exact, *QSCALE folded
__device__ float g_k[B_*H_*N_*DH_];      // [b,h,n,d] tf32-exact
__device__ float g_v[B_*H_*DH_*N_];      // [b,h,d,n] TRANSPOSED, tf32-exact
__device__ float g_att[B_*N_*DI_];       // full f32
__device__ float g_gated[B_*N_*DI_];     // gate GEMM raw acc, then gated tf32
// tf32-rounded inputs (prepass); weights stored TRANSPOSED [out][in]
__device__ float g_seq[B_*N_*D_];
__device__ float g_wqkv[3*DI_*D_];       // row n: n<1024 Wq^T, else Wkv^T
__device__ float g_wg [DI_*D_];
__device__ float g_wo [D_*DI_];

// ---------------------------------------------------------------------------
// helpers
// ---------------------------------------------------------------------------
__device__ __forceinline__ unsigned f2tf(float x) {
    unsigned r;
    asm("cvt.rna.tf32.f32 %0, %1;" : "=r"(r) : "f"(x));
    return r;
}
__device__ __forceinline__ float f2tff(float x) {
    return __uint_as_float(f2tf(x));
}
__device__ __forceinline__ float ex2f(float x) {
    float y;
    asm("ex2.approx.f32 %0, %1;" : "=f"(y) : "f"(x));
    return y;
}

__device__ __forceinline__ void mma8(float* c, const unsigned* a, const unsigned* b) {
    asm volatile(
        "mma.sync.aligned.m16n8k8.row.col.f32.tf32.tf32.f32 "
        "{%0,%1,%2,%3},{%4,%5,%6,%7},{%8,%9},{%0,%1,%2,%3};"
        : "+f"(c[0]), "+f"(c[1]), "+f"(c[2]), "+f"(c[3])
        : "r"(a[0]), "r"(a[1]), "r"(a[2]), "r"(a[3]), "r"(b[0]), "r"(b[1]));
}

__device__ __forceinline__ unsigned sptr(const void* p) {
    return (unsigned)__cvta_generic_to_shared(p);
}
#define CP16(dst, src) \
    asm volatile("cp.async.cg.shared.global [%0], [%1], 16;" :: "r"(dst), "l"(src))
#define CP_COMMIT() asm volatile("cp.async.commit_group;" ::: "memory")
#define CP_WAIT(n)  asm volatile("cp.async.wait_group %0;" :: "n"(n) : "memory")
#define LDSM4(r0, r1, r2, r3, addr) \
    asm volatile("ldmatrix.sync.aligned.m8n8.x4.shared.b16 {%0,%1,%2,%3}, [%4];" \
        : "=r"(r0), "=r"(r1), "=r"(r2), "=r"(r3) : "r"(addr))

// ---------------------------------------------------------------------------
// Prepass A: round seq to tf32-exact
// ---------------------------------------------------------------------------
__global__ void prep_seq_kernel(const float4* __restrict__ seq)
{
    const int i = blockIdx.x * blockDim.x + threadIdx.x;
    if (i >= B_*N_*D_/4) return;
    float4 v = seq[i];
    v.x = f2tff(v.x); v.y = f2tff(v.y); v.z = f2tff(v.z); v.w = f2tff(v.w);
    ((float4*)g_seq)[i] = v;
}

// ---------------------------------------------------------------------------
// Prepass B: transpose + round weights. In [1024][W] -> out [W][1024].
// ---------------------------------------------------------------------------
__global__ void prep_wT_kernel(const float* __restrict__ wq,
                               const float* __restrict__ wkv,
                               const float* __restrict__ wg,
                               const float* __restrict__ wo)
{
    __shared__ float t[32][33];
    int tt = blockIdx.x;
    const float* src;
    float* dst;
    int W, kt, nt, noff;
    if (tt < 1024)      { src = wq;  dst = g_wqkv; W = 1024; nt = tt & 31; kt = tt >> 5; noff = 0; }
    else if (tt < 3072) { tt -= 1024; src = wkv; dst = g_wqkv; W = 2048; nt = tt & 63; kt = tt >> 6; noff = 1024; }
    else if (tt < 4096) { tt -= 3072; src = wg;  dst = g_wg;  W = 1024; nt = tt & 31; kt = tt >> 5; noff = 0; }
    else                { tt -= 4096; src = wo;  dst = g_wo;  W = 1024; nt = tt & 31; kt = tt >> 5; noff = 0; }
    const int tx = threadIdx.x & 31, ty = threadIdx.x >> 5;
    #pragma unroll
    for (int i = 0; i < 4; i++)
        t[ty + 8*i][tx] = f2tff(src[(size_t)(kt*32 + ty + 8*i) * W + nt*32 + tx]);
    __syncthreads();
    #pragma unroll
    for (int i = 0; i < 4; i++)
        dst[(size_t)(noff + nt*32 + ty + 8*i) * 1024 + kt*32 + tx] = t[tx][ty + 8*i];
}

// ---------------------------------------------------------------------------
// Gating: g_gated = round_tf32(g_att * sigmoid(g_gated + bg))  (in-place)
// Expression identical to the old fused MODE2 epilogue -> bit-identical.
// ---------------------------------------------------------------------------
__global__ void gating_kernel(const float* __restrict__ bg)
{
    const int i = blockIdx.x * blockDim.x + threadIdx.x;
    if (i >= B_*N_*DI_/4) return;
    float4 a = ((const float4*)g_att)[i];
    float4 g = ((float4*)g_gated)[i];
    const int c = (i * 4) & (DI_ - 1);
    float4 bb = *(const float4*)&bg[c];
    g.x = f2tff(a.x / (1.f + __expf(-(g.x + bb.x))));
    g.y = f2tff(a.y / (1.f + __expf(-(g.y + bb.y))));
    g.z = f2tff(a.z / (1.f + __expf(-(g.z + bb.z))));
    g.w = f2tff(a.w / (1.f + __expf(-(g.w + bb.w))));
    ((float4*)g_gated)[i] = g;
}

// ---------------------------------------------------------------------------
// tf32 GEMM, 3-stage cp.async, ldmatrix fragment loads.
// C[M,NN] = A[M,K] @ W^T  where Wt is [NN][K] (weights pre-transposed).
// MODE 0: fused QKV -> g_q(*QSCALE)/g_k (head split) + g_v TRANSPOSED
// MODE 2: gate GEMM, raw acc -> g_gated (gating applied later)
// MODE 3: out -> out (plain f32)
// ---------------------------------------------------------------------------
#define GA 4608
#define GB 4608
#define GSTAGES 3
#define GEMM_SMEM_BYTES (GSTAGES * (GA + GB) * 4)

template<int MODE>
__global__ void __launch_bounds__(256, 2) tgemm_kernel(
    const float* __restrict__ A, const float* __restrict__ Wt,
    int K, int NN, const float* __restrict__ bg, float* __restrict__ out)
{
    extern __shared__ unsigned smu[];

    const int tid  = threadIdx.x;
    const int wid  = tid >> 5;
    const int lane = tid & 31;
    const int lr   = lane >> 2;
    const int lc   = lane & 3;
    const int wm   = wid >> 2;
    const int wn   = wid & 3;
    const int row0 = blockIdx.y * 128;
    const int col0 = blockIdx.x * 128;

    const int ar = tid >> 3, ac = (tid & 7) * 4;

    const int arow_l = ((lane >> 3) & 1) * 8 + (lane & 7);
    const int akof_l = ((lane >> 4) & 1) * 4;
    const int brow_l = ((lane >> 4) & 1) * 8 + (lane & 7);
    const int bkof_l = ((lane >> 3) & 1) * 4;
    const unsigned sbase = sptr(smu);
    const unsigned aOff = ((wm * 64 + arow_l) * 36 + akof_l) * 4;
    const unsigned bOff = (GA + (wn * 32 + brow_l) * 36 + bkof_l) * 4;

    float acc[4][4][4];
    #pragma unroll
    for (int mf = 0; mf < 4; mf++)
        #pragma unroll
        for (int nf = 0; nf < 4; nf++)
            #pragma unroll
            for (int e = 0; e < 4; e++) acc[mf][nf][e] = 0.f;

    auto loadChunk = [&](int k0, int buf) {
        unsigned* Ad = smu + buf * (GA + GB);
        unsigned* Bd = Ad + GA;
        #pragma unroll
        for (int it = 0; it < 4; it++) {
            const int r = ar + it * 32;
            CP16(sptr(&Ad[r * 36 + ac]),
                 &A[(size_t)(row0 + r) * K + k0 + ac]);
        }
        #pragma unroll
        for (int it = 0; it < 4; it++) {
            const int r = ar + it * 32;
            CP16(sptr(&Bd[r * 36 + ac]),
                 &Wt[(size_t)(col0 + r) * K + k0 + ac]);
        }
        CP_COMMIT();
    };

    const int nch = K >> 5;
    loadChunk(0, 0);
    loadChunk(32, 1);

    int buf = 0;
    for (int ch = 0; ch < nch; ch++) {
        if (ch + 1 < nch) { CP_WAIT(1); } else { CP_WAIT(0); }
        __syncthreads();
        if (ch + 2 < nch)
            loadChunk((ch + 2) * 32, (buf + 2) % GSTAGES);

        const unsigned cbase = sbase + buf * ((GA + GB) * 4);
        #pragma unroll
        for (int ks = 0; ks < 4; ks++) {
            unsigned a[4][4], b[4][2];
            #pragma unroll
            for (int mf = 0; mf < 4; mf++)
                LDSM4(a[mf][0], a[mf][1], a[mf][2], a[mf][3],
                      cbase + aOff + mf * (16*36*4) + ks * 32);
            #pragma unroll
            for (int p = 0; p < 2; p++)
                LDSM4(b[2*p][0], b[2*p][1], b[2*p+1][0], b[2*p+1][1],
                      cbase + bOff + p * (16*36*4) + ks * 32);
            #pragma unroll
            for (int mf = 0; mf < 4; mf++)
                #pragma unroll
                for (int nf = 0; nf < 4; nf++)
                    mma8(acc[mf][nf], a[mf], b[nf]);
        }
        buf = (buf + 1) % GSTAGES;
    }

    // Epilogue
    #pragma unroll
    for (int mf = 0; mf < 4; mf++) {
        #pragma unroll
        for (int hf = 0; hf < 2; hf++) {
            const int m  = row0 + wm * 64 + mf * 16 + lr + hf * 8;
            const int bb = m >> 11;
            const int ii = m & 2047;
            #pragma unroll
            for (int nf = 0; nf < 4; nf++) {
                const int col = col0 + wn * 32 + nf * 8 + 2 * lc;
                float2 v = make_float2(acc[mf][nf][hf * 2], acc[mf][nf][hf * 2 + 1]);
                if (MODE == 0) {
                    if (col < DI_) {            // Q (scale*log2e folded)
                        v.x = f2tff(v.x * QSCALE_); v.y = f2tff(v.y * QSCALE_);
                        const int hh = col >> 6, dd = col & 63;
                        *(float2*)&g_q[(((size_t)(bb * H_ + hh)) * N_ + ii) * DH_ + dd] = v;
                    } else if (col < 2 * DI_) { // K
                        v.x = f2tff(v.x); v.y = f2tff(v.y);
                        const int c = col - DI_;
                        const int hh = c >> 6, dd = c & 63;
                        *(float2*)&g_k[(((size_t)(bb * H_ + hh)) * N_ + ii) * DH_ + dd] = v;
                    } else {                    // V -> transposed [b,h,d,n]
                        const int c = col - 2 * DI_;
                        const int hh = c >> 6, dd = c & 63;
                        float* vb = &g_v[(((size_t)(bb * H_ + hh)) * DH_ + dd) * N_ + ii];
                        vb[0]  = f2tff(v.x);
                        vb[N_] = f2tff(v.y);
                    }
                } else if (MODE == 2) {
                    // raw accumulator; gating applied by gating_kernel later
                    *(float2*)&g_gated[(size_t)m * DI_ + col] = v;
                } else {
                    *(float2*)&out[(size_t)m * D_ + col] = v;
                }
            }
        }
    }
}

// ---------------------------------------------------------------------------
// Flash attention, tf32 + ldmatrix, base-2 softmax.  (unchanged from R10)
// ---------------------------------------------------------------------------
#define AQ (128 * 68)
#define AK (64 * 68)
#define AV (64 * 68)
#define AP (128 * 68)
#define ATT_SMEM_BYTES ((AQ + AK + AV + AP) * 4)

__global__ void __launch_bounds__(256, 2) fattn_kernel(
    const float* __restrict__ bias, const int* __restrict__ mask)
{
    extern __shared__ unsigned sm[];
    unsigned* Qs = sm;
    unsigned* Ks = Qs + AQ;
    unsigned* Vs = Ks + AK;
    unsigned* Ps = Vs + AV;

    const int tid  = threadIdx.x;
    const int wid  = tid >> 5;
    const int lane = tid & 31;
    const int lr   = lane >> 2;
    const int lc   = lane & 3;
    const int bh   = blockIdx.y;
    const int b    = bh >> 4;
    const int h    = bh & 15;
    const int i0   = blockIdx.x * 128;
    const int q0   = wid * 16;

    const unsigned* qbase = (const unsigned*)(g_q + ((size_t)bh * N_ + i0) * DH_);
    const float* kbase = g_k + (size_t)bh * N_ * DH_;
    const float* vbase = g_v + (size_t)bh * DH_ * N_;
    const float* bp0 = bias + ((size_t)bh * N_ + i0 + q0 + lr) * N_;
    const float* bp1 = bp0 + 8 * (size_t)N_;
    const int* mbase = mask + (size_t)b * N_;

    const int lrow = tid >> 2;
    const int lcol = (tid & 3) * 4;

    const int arow_l = ((lane >> 3) & 1) * 8 + (lane & 7);
    const int akof_l = ((lane >> 4) & 1) * 4;
    const int brow_l = ((lane >> 4) & 1) * 8 + (lane & 7);
    const int bkof_l = ((lane >> 3) & 1) * 4;
    const unsigned qAddr = sptr(Qs) + ((q0 + arow_l) * 68 + akof_l) * 4;
    const unsigned kAddr = sptr(Ks) + (brow_l * 68 + bkof_l) * 4;
    const unsigned vAddr = sptr(Vs) + (brow_l * 68 + bkof_l) * 4;
    const unsigned pAddr = sptr(Ps) + ((q0 + arow_l) * 68 + akof_l) * 4;

    #pragma unroll
    for (int it = 0; it < 4; it++) {
        const int c4 = lcol + it * 16;
        CP16(sptr(&Ks[lrow * 68 + c4]), &kbase[(size_t)lrow * DH_ + c4]);
    }
    CP_COMMIT();

    #pragma unroll
    for (int it = 0; it < 8; it++) {
        const int i = tid + it * 256;
        const int r = i >> 4, c4 = (i & 15) * 4;
        *(uint4*)&Qs[r * 68 + c4] = *(const uint4*)&qbase[r * DH_ + c4];
    }

    float S[8][4], O[8][4];
    float mi0 = -1e30f, mi1 = -1e30f, li0 = 0.f, li1 = 0.f;
    #pragma unroll
    for (int nf = 0; nf < 8; nf++)
        O[nf][0] = O[nf][1] = O[nf][2] = O[nf][3] = 0.f;

    const int NT = N_ / 64;
    for (int t = 0; t < NT; t++) {
        const int j0 = t * 64;
        CP_WAIT(0);
        __syncthreads();

        #pragma unroll
        for (int it = 0; it < 4; it++) {
            const int c4 = lcol + it * 16;
            CP16(sptr(&Vs[lrow * 68 + c4]), &vbase[(size_t)lrow * N_ + j0 + c4]);
        }
        CP_COMMIT();

        float2 bA[8], bB[8];
        #pragma unroll
        for (int nf = 0; nf < 8; nf++) {
            const int jc = nf * 8 + 2 * lc;
            int2  mv = *(const int2*)&mbase[j0 + jc];
            float2 t0 = *(const float2*)&bp0[j0 + jc];
            float2 t1 = *(const float2*)&bp1[j0 + jc];
            const float mx = mv.x ? 0.f : -1e30f;
            const float my = mv.y ? 0.f : -1e30f;
            bA[nf].x = fmaf(t0.x, LOG2E_, mx); bA[nf].y = fmaf(t0.y, LOG2E_, my);
            bB[nf].x = fmaf(t1.x, LOG2E_, mx); bB[nf].y = fmaf(t1.y, LOG2E_, my);
        }

        #pragma unroll
        for (int nf = 0; nf < 8; nf++)
            S[nf][0] = S[nf][1] = S[nf][2] = S[nf][3] = 0.f;
        #pragma unroll
        for (int ks = 0; ks < 8; ks++) {
            unsigned a[4];
            LDSM4(a[0], a[1], a[2], a[3], qAddr + ks * 32);
            #pragma unroll
            for (int p = 0; p < 4; p++) {
                unsigned bf[4];
                LDSM4(bf[0], bf[1], bf[2], bf[3],
                      kAddr + p * (16*68*4) + ks * 32);
                mma8(S[2*p],     a, &bf[0]);
                mma8(S[2*p + 1], a, &bf[2]);
            }
        }

        __syncthreads();
        if (t + 1 < NT) {
            #pragma unroll
            for (int it = 0; it < 4; it++) {
                const int c4 = lcol + it * 16;
                CP16(sptr(&Ks[lrow * 68 + c4]),
                     &kbase[(size_t)(j0 + 64 + lrow) * DH_ + c4]);
            }
        }
        CP_COMMIT();

        #pragma unroll
        for (int nf = 0; nf < 8; nf++) {
            S[nf][0] += bA[nf].x; S[nf][1] += bA[nf].y;
            S[nf][2] += bB[nf].x; S[nf][3] += bB[nf].y;
        }

        float m0 = -1e30f, m1 = -1e30f;
        #pragma unroll
        for (int nf = 0; nf < 8; nf++) {
            m0 = fmaxf(m0, fmaxf(S[nf][0], S[nf][1]));
            m1 = fmaxf(m1, fmaxf(S[nf][2], S[nf][3]));
        }
        m0 = fmaxf(m0, __shfl_xor_sync(~0u, m0, 1));
        m0 = fmaxf(m0, __shfl_xor_sync(~0u, m0, 2));
        m1 = fmaxf(m1, __shfl_xor_sync(~0u, m1, 1));
        m1 = fmaxf(m1, __shfl_xor_sync(~0u, m1, 2));

        const float mn0 = fmaxf(mi0, m0), mn1 = fmaxf(mi1, m1);
        const float cr0 = ex2f(mi0 - mn0), cr1 = ex2f(mi1 - mn1);
        mi0 = mn0; mi1 = mn1;

        float s0 = 0.f, s1 = 0.f;
        #pragma unroll
        for (int nf = 0; nf < 8; nf++) {
            S[nf][0] = ex2f(S[nf][0] - mn0);
            S[nf][1] = ex2f(S[nf][1] - mn0);
            S[nf][2] = ex2f(S[nf][2] - mn1);
            S[nf][3] = ex2f(S[nf][3] - mn1);
            s0 += S[nf][0] + S[nf][1];
            s1 += S[nf][2] + S[nf][3];
            O[nf][0] *= cr0; O[nf][1] *= cr0;
            O[nf][2] *= cr1; O[nf][3] *= cr1;
            uint2 u0 = make_uint2(f2tf(S[nf][0]), f2tf(S[nf][1]));
            *(uint2*)&Ps[(q0 + lr) * 68 + nf * 8 + 2 * lc] = u0;
            uint2 u1 = make_uint2(f2tf(S[nf][2]), f2tf(S[nf][3]));
            *(uint2*)&Ps[(q0 + lr + 8) * 68 + nf * 8 + 2 * lc] = u1;
        }
        s0 += __shfl_xor_sync(~0u, s0, 1);
        s0 += __shfl_xor_sync(~0u, s0, 2);
        s1 += __shfl_xor_sync(~0u, s1, 1);
        s1 += __shfl_xor_sync(~0u, s1, 2);
        li0 = li0 * cr0 + s0;
        li1 = li1 * cr1 + s1;

        __syncwarp();

        CP_WAIT(1);
        __syncthreads();

        #pragma unroll
        for (int ks = 0; ks < 8; ks++) {
            unsigned a[4];
            LDSM4(a[0], a[1], a[2], a[3], pAddr + ks * 32);
            #pragma unroll
            for (int p = 0; p < 4; p++) {
                unsigned bf[4];
                LDSM4(bf[0], bf[1], bf[2], bf[3],
                      vAddr + p * (16*68*4) + ks * 32);
                mma8(O[2*p],     a, &bf[0]);
                mma8(O[2*p + 1], a, &bf[2]);
            }
        }
    }

    const float inv0 = 1.f / li0, inv1 = 1.f / li1;
    const size_t r0 = ((size_t)b * N_ + i0 + q0 + lr) * DI_ + h * DH_;
    const size_t r1 = r0 + 8 * (size_t)DI_;
    #pragma unroll
    for (int nf = 0; nf < 8; nf++) {
        const int dd = nf * 8 + 2 * lc;
        *(float2*)&g_att[r0 + dd] = make_float2(O[nf][0] * inv0, O[nf][1] * inv0);
        *(float2*)&g_att[r1 + dd] = make_float2(O[nf][2] * inv1, O[nf][3] * inv1);
    }
}

// ---------------------------------------------------------------------------
extern "C" void kernel_launch(void* const* d_in, const int* in_sizes, int n_in,
                              void* d_out, int out_size)
{
    const float* seq  = (const float*)d_in[0];
    const int*   mask = (const int*)d_in[1];
    const float* bias = (const float*)d_in[2];
    const float* Wq   = (const float*)d_in[3];
    const float* Wkv  = (const float*)d_in[4];
    const float* Wo   = (const float*)d_in[5];
    const float* Wg   = (const float*)d_in[6];
    const float* bg   = (const float*)d_in[7];
    float* out = (float*)d_out;

    // One-time resource init (uncaptured first call; enqueued work per call
    // is identical every call — determinism contract preserved).
    static cudaStream_t s1 = nullptr;
    static cudaEvent_t evPrep = nullptr, evGate = nullptr;
    if (s1 == nullptr) {
        cudaStreamCreateWithFlags(&s1, cudaStreamNonBlocking);
        cudaEventCreateWithFlags(&evPrep, cudaEventDisableTiming);
        cudaEventCreateWithFlags(&evGate, cudaEventDisableTiming);
        cudaFuncSetAttribute(tgemm_kernel<0>,
            cudaFuncAttributeMaxDynamicSharedMemorySize, GEMM_SMEM_BYTES);
        cudaFuncSetAttribute(tgemm_kernel<2>,
            cudaFuncAttributeMaxDynamicSharedMemorySize, GEMM_SMEM_BYTES);
        cudaFuncSetAttribute(tgemm_kernel<3>,
            cudaFuncAttributeMaxDynamicSharedMemorySize, GEMM_SMEM_BYTES);
        cudaFuncSetAttribute(fattn_kernel,
            cudaFuncAttributeMaxDynamicSharedMemorySize, ATT_SMEM_BYTES);
    }

    float *p_seq, *p_wqkv, *p_wg, *p_wo, *p_gated;
    cudaGetSymbolAddress((void**)&p_seq,   g_seq);
    cudaGetSymbolAddress((void**)&p_wqkv,  g_wqkv);
    cudaGetSymbolAddress((void**)&p_wg,    g_wg);
    cudaGetSymbolAddress((void**)&p_wo,    g_wo);
    cudaGetSymbolAddress((void**)&p_gated, g_gated);

    // Prepass (main stream)
    prep_seq_kernel<<<(B_*N_*D_/4 + 255) / 256, 256>>>((const float4*)seq);
    prep_wT_kernel<<<5120, 256>>>(Wq, Wkv, Wg, Wo);
    cudaEventRecord(evPrep, 0);

    // Main stream: QKV projection -> attention
    tgemm_kernel<0><<<dim3(3 * DI_ / 128, (B_ * N_) / 128), 256, GEMM_SMEM_BYTES>>>(
        p_seq, p_wqkv, D_, 3 * DI_, nullptr, nullptr);
    fattn_kernel<<<dim3(N_ / 128, B_ * H_), 256, ATT_SMEM_BYTES>>>(bias, mask);

    // Side stream: gate GEMM (independent of QKV/attention), overlapped
    cudaStreamWaitEvent(s1, evPrep, 0);
    tgemm_kernel<2><<<dim3(DI_ / 128, (B_ * N_) / 128), 256, GEMM_SMEM_BYTES, s1>>>(
        p_seq, p_wg, D_, DI_, nullptr, nullptr);
    cudaEventRecord(evGate, s1);

    // Join: gating (needs g_att + gate acc), then output projection
    cudaStreamWaitEvent(0, evGate, 0);
    gating_kernel<<<(B_*N_*DI_/4 + 255) / 256, 256>>>(bg);
    tgemm_kernel<3><<<dim3(D_ / 128, (B_ * N_) / 128), 256, GEMM_SMEM_BYTES>>>(
        p_gated, p_wo, DI_, D_, nullptr, out);
}